// round 1
// baseline (speedup 1.0000x reference)
#include <cuda_runtime.h>
#include <mma.h>

using namespace nvcuda;

#define B_  16
#define N_  192
#define H_  128
#define F_  128
#define G_  50
#define GP  64      // G padded to multiple of 8 (tf32 k) and nice stride
#define JT  32      // neighbor tile

// scratch for precomputed neighbor features nf = features @ W_f + b_f  [B*N, F]
__device__ float g_nf[B_ * N_ * F_];

__device__ __forceinline__ float softplus_f(float x) {
    // stable log(1+exp(x))
    return fmaxf(x, 0.0f) + log1pf(expf(-fabsf(x)));
}

// ---------------------------------------------------------------------------
// Kernel 1: nf[b*N+j, f] = sum_h features[b,j,h] * W_f[h,f] + b_f[f]
// grid = B*N blocks, 128 threads
// ---------------------------------------------------------------------------
__global__ __launch_bounds__(128)
void nf_kernel(const float* __restrict__ features,
               const float* __restrict__ W_f,
               const float* __restrict__ b_f) {
    __shared__ float fs[H_];
    const int row = blockIdx.x;        // b*N + j
    const int f   = threadIdx.x;       // 0..127
    fs[f] = features[(size_t)row * H_ + f];
    __syncthreads();
    float acc = b_f[f];
#pragma unroll 8
    for (int h = 0; h < H_; ++h) {
        acc = fmaf(fs[h], W_f[h * F_ + f], acc);
    }
    g_nf[(size_t)row * F_ + f] = acc;
}

// ---------------------------------------------------------------------------
// Kernel 2: fused filter-net + masked aggregation + output MLP + residual
// One CTA per central atom (b,i). 256 threads = 8 warps.
//
// SMEM layout (floats):
//   W1s   [GP][F_]    8192   (G rows zero-padded to 64)
//   W2s   [F_][F_]   16384
//   rbf_s [JT][GP]    2048
//   h_s   [JT][F_]    4096   (also reused for agg vector in epilogue)
//   fw_s  [JT][F_]    4096   (also reused for t1 vector in epilogue)
//   red   [256]        256
// total 35072 floats = 140288 bytes (dynamic)
// ---------------------------------------------------------------------------
#define OFF_W1   0
#define OFF_W2   (OFF_W1 + GP * F_)
#define OFF_RBF  (OFF_W2 + F_ * F_)
#define OFF_H    (OFF_RBF + JT * GP)
#define OFF_FW   (OFF_H + JT * F_)
#define OFF_RED  (OFF_FW + JT * F_)
#define SMEM_FLOATS (OFF_RED + 256)

__global__ __launch_bounds__(256)
void interaction_kernel(const float* __restrict__ rbf,
                        const int*   __restrict__ nmask,
                        const float* __restrict__ W1,
                        const float* __restrict__ b1,
                        const float* __restrict__ W2,
                        const float* __restrict__ b2,
                        const float* __restrict__ Wo1,
                        const float* __restrict__ bo1,
                        const float* __restrict__ Wo2,
                        const float* __restrict__ bo2,
                        const float* __restrict__ features,
                        float*       __restrict__ out) {
    extern __shared__ float smem[];
    float* W1s   = smem + OFF_W1;
    float* W2s   = smem + OFF_W2;
    float* rbf_s = smem + OFF_RBF;
    float* h_s   = smem + OFF_H;
    float* fw_s  = smem + OFF_FW;
    float* red   = smem + OFF_RED;

    const int bi  = blockIdx.x;           // b*N + i
    const int b   = bi / N_;
    const int tid = threadIdx.x;
    const int warp = tid >> 5;

    // ---- stage weights (zero-pad W1 rows 50..63) ----
    for (int idx = tid; idx < GP * F_; idx += 256) {
        const int g = idx >> 7;           // row (GP stride == F_ == 128)
        const int f = idx & 127;
        W1s[idx] = (g < G_) ? W1[g * F_ + f] : 0.0f;
    }
    for (int idx = tid; idx < F_ * F_; idx += 256) {
        W2s[idx] = W2[idx];
    }

    const float* rbf_base  = rbf + (size_t)bi * N_ * G_;
    const int*   mask_base = nmask + (size_t)bi * N_;

    const int f_e  = tid & 127;    // feature owned in elementwise phase
    const int half = tid >> 7;     // 0/1: which half of the j rows
    const float b2r = b2[f_e];
    float agg = 0.0f;

    // warp-tile assignment: 2 m-tiles x 8 n-tiles of 16x16; each warp owns 2
    const int mt = warp >> 2;            // 0 or 1
    const int nt = (warp & 3) * 2;       // 0,2,4,6

    __syncthreads();

    for (int j0 = 0; j0 < N_; j0 += JT) {
        __syncthreads();   // previous iteration fully consumed

        // ---- load rbf tile [JT][GP], zero-pad g>=50 ----
        for (int idx = tid; idx < JT * GP; idx += 256) {
            const int jj = idx >> 6;
            const int g  = idx & 63;
            rbf_s[idx] = (g < G_) ? rbf_base[(size_t)(j0 + jj) * G_ + g] : 0.0f;
        }
        __syncthreads();

        // ---- GEMM1: [JT,GP] @ [GP,F] -> h_s (pre-activation) ----
        {
            wmma::fragment<wmma::accumulator, 16, 16, 8, float> c0, c1;
            wmma::fill_fragment(c0, 0.0f);
            wmma::fill_fragment(c1, 0.0f);
#pragma unroll
            for (int k = 0; k < GP; k += 8) {
                wmma::fragment<wmma::matrix_a, 16, 16, 8, wmma::precision::tf32, wmma::row_major> a;
                wmma::load_matrix_sync(a, rbf_s + mt * 16 * GP + k, GP);
#pragma unroll
                for (int t = 0; t < a.num_elements; ++t) a.x[t] = wmma::__float_to_tf32(a.x[t]);
                wmma::fragment<wmma::matrix_b, 16, 16, 8, wmma::precision::tf32, wmma::row_major> bb0, bb1;
                wmma::load_matrix_sync(bb0, W1s + k * F_ + nt * 16, F_);
                wmma::load_matrix_sync(bb1, W1s + k * F_ + (nt + 1) * 16, F_);
#pragma unroll
                for (int t = 0; t < bb0.num_elements; ++t) bb0.x[t] = wmma::__float_to_tf32(bb0.x[t]);
#pragma unroll
                for (int t = 0; t < bb1.num_elements; ++t) bb1.x[t] = wmma::__float_to_tf32(bb1.x[t]);
                wmma::mma_sync(c0, a, bb0, c0);
                wmma::mma_sync(c1, a, bb1, c1);
            }
            wmma::store_matrix_sync(h_s + mt * 16 * F_ + nt * 16, c0, F_, wmma::mem_row_major);
            wmma::store_matrix_sync(h_s + mt * 16 * F_ + (nt + 1) * 16, c1, F_, wmma::mem_row_major);
        }
        __syncthreads();

        // ---- softplus(+b1) in place ----
        for (int idx = tid; idx < JT * F_; idx += 256) {
            h_s[idx] = softplus_f(h_s[idx] + b1[idx & 127]);
        }
        __syncthreads();

        // ---- GEMM2: [JT,F] @ [F,F] -> fw_s ----
        {
            wmma::fragment<wmma::accumulator, 16, 16, 8, float> c0, c1;
            wmma::fill_fragment(c0, 0.0f);
            wmma::fill_fragment(c1, 0.0f);
#pragma unroll
            for (int k = 0; k < F_; k += 8) {
                wmma::fragment<wmma::matrix_a, 16, 16, 8, wmma::precision::tf32, wmma::row_major> a;
                wmma::load_matrix_sync(a, h_s + mt * 16 * F_ + k, F_);
#pragma unroll
                for (int t = 0; t < a.num_elements; ++t) a.x[t] = wmma::__float_to_tf32(a.x[t]);
                wmma::fragment<wmma::matrix_b, 16, 16, 8, wmma::precision::tf32, wmma::row_major> bb0, bb1;
                wmma::load_matrix_sync(bb0, W2s + k * F_ + nt * 16, F_);
                wmma::load_matrix_sync(bb1, W2s + k * F_ + (nt + 1) * 16, F_);
#pragma unroll
                for (int t = 0; t < bb0.num_elements; ++t) bb0.x[t] = wmma::__float_to_tf32(bb0.x[t]);
#pragma unroll
                for (int t = 0; t < bb1.num_elements; ++t) bb1.x[t] = wmma::__float_to_tf32(bb1.x[t]);
                wmma::mma_sync(c0, a, bb0, c0);
                wmma::mma_sync(c1, a, bb1, c1);
            }
            wmma::store_matrix_sync(fw_s + mt * 16 * F_ + nt * 16, c0, F_, wmma::mem_row_major);
            wmma::store_matrix_sync(fw_s + mt * 16 * F_ + (nt + 1) * 16, c1, F_, wmma::mem_row_major);
        }
        __syncthreads();

        // ---- masked elementwise multiply with nf, accumulate over j ----
        {
            const float* nf_row = g_nf + ((size_t)(b * N_ + j0 + half)) * F_ + f_e;
#pragma unroll 4
            for (int jj = half; jj < JT; jj += 2) {
                const int m = mask_base[j0 + jj];
                if (m) {
                    const float fw = fw_s[jj * F_ + f_e] + b2r;
                    agg = fmaf(fw, nf_row[(size_t)(jj - half) * F_], agg);
                }
            }
        }
    }

    // ---- reduce the two halves ----
    red[tid] = agg;
    __syncthreads();
    if (tid < 128) {
        h_s[tid] = red[tid] + red[tid + 128];   // agg vector in h_s[0..127]
    }
    __syncthreads();

    // ---- output MLP: softplus(agg @ Wo1 + bo1) @ Wo2 + bo2 + residual ----
    float t1 = 0.0f;
    if (tid < 128) {
        t1 = bo1[tid];
#pragma unroll 8
        for (int f = 0; f < F_; ++f) {
            t1 = fmaf(h_s[f], Wo1[f * H_ + tid], t1);
        }
        t1 = softplus_f(t1);
    }
    __syncthreads();
    if (tid < 128) fw_s[tid] = t1;
    __syncthreads();
    if (tid < 128) {
        float o = bo2[tid];
#pragma unroll 8
        for (int f = 0; f < F_; ++f) {
            o = fmaf(fw_s[f], Wo2[f * H_ + tid], o);
        }
        out[(size_t)bi * H_ + tid] = o + features[(size_t)bi * H_ + tid];
    }
}

// ---------------------------------------------------------------------------
// launch
// ---------------------------------------------------------------------------
extern "C" void kernel_launch(void* const* d_in, const int* in_sizes, int n_in,
                              void* d_out, int out_size) {
    const float* features = (const float*)d_in[0];
    const float* rbf      = (const float*)d_in[1];
    const int*   nmask    = (const int*)  d_in[2];
    const float* W_rbf1   = (const float*)d_in[3];
    const float* b_rbf1   = (const float*)d_in[4];
    const float* W_rbf2   = (const float*)d_in[5];
    const float* b_rbf2   = (const float*)d_in[6];
    const float* W_f      = (const float*)d_in[7];
    const float* b_f      = (const float*)d_in[8];
    const float* W_o1     = (const float*)d_in[9];
    const float* b_o1     = (const float*)d_in[10];
    const float* W_o2     = (const float*)d_in[11];
    const float* b_o2     = (const float*)d_in[12];
    float* out = (float*)d_out;

    const int smem_bytes = SMEM_FLOATS * sizeof(float);
    cudaFuncSetAttribute(interaction_kernel,
                         cudaFuncAttributeMaxDynamicSharedMemorySize, smem_bytes);

    nf_kernel<<<B_ * N_, 128>>>(features, W_f, b_f);
    interaction_kernel<<<B_ * N_, 256, smem_bytes>>>(
        rbf, nmask, W_rbf1, b_rbf1, W_rbf2, b_rbf2,
        W_o1, b_o1, W_o2, b_o2, features, out);
}

// round 2
// speedup vs baseline: 1.8924x; 1.8924x over previous
#include <cuda_runtime.h>
#include <mma.h>

using namespace nvcuda;

#define B_  16
#define N_  192
#define H_  128
#define F_  128
#define G_  50
#define JT  64      // neighbor tile (rows per outer iteration)
#define NT  3       // N_/JT

// padded row strides (floats) to dodge smem bank conflicts
#define LDW  132    // W1s/W2s/h_s/fw_s row stride (128+4)
#define LDR  68     // rbf_s row stride (64+4)

// scratch: nf = features @ W_f + b_f  [B*N, F]
__device__ float g_nf[B_ * N_ * F_];

__device__ __forceinline__ float softplus_fast(float x) {
    // max(x,0) + log(1 + e^{-|x|}) via MUFU.EX2 / MUFU.LG2
    float ax = fabsf(x);
    float e  = __expf(-ax);
    float l  = __logf(1.0f + e);
    return fmaxf(x, 0.0f) + l;
}

__device__ __forceinline__ float to_tf32(float x) {
    return wmma::__float_to_tf32(x);
}

// ---------------------------------------------------------------------------
// Kernel 1: nf[b*N+j, f] = sum_h features[b,j,h] * W_f[h,f] + b_f[f]
// ---------------------------------------------------------------------------
__global__ __launch_bounds__(128)
void nf_kernel(const float* __restrict__ features,
               const float* __restrict__ W_f,
               const float* __restrict__ b_f) {
    __shared__ float fs[H_];
    const int row = blockIdx.x;
    const int f   = threadIdx.x;
    fs[f] = features[(size_t)row * H_ + f];
    __syncthreads();
    float acc = b_f[f];
#pragma unroll 8
    for (int h = 0; h < H_; ++h) {
        acc = fmaf(fs[h], W_f[h * F_ + f], acc);
    }
    g_nf[(size_t)row * F_ + f] = acc;
}

// ---------------------------------------------------------------------------
// Kernel 2: fused filter-net + masked aggregation + output MLP + residual
// One CTA per central atom (b,i). 256 threads = 8 warps.
// SMEM (floats):
//   W1s   [64][LDW]   (tf32, G rows zero-padded to 64)
//   W2s   [128][LDW]  (tf32)
//   rbf_s [JT][LDR]   (tf32, cols 50..63 zero)
//   h_s   [JT][LDW]
//   fw_s  [JT][LDW]
//   red   [256]       (also mask cache[64] during the loop)
// ---------------------------------------------------------------------------
#define OFF_W1   0
#define OFF_W2   (OFF_W1 + 64 * LDW)
#define OFF_RBF  (OFF_W2 + 128 * LDW)
#define OFF_H    (OFF_RBF + JT * LDR)
#define OFF_FW   (OFF_H + JT * LDW)
#define OFF_RED  (OFF_FW + JT * LDW)
#define SMEM_FLOATS (OFF_RED + 256)

#define TILE_ELEMS (JT * G_)          // 3200
#define PRE_N 13                      // ceil(3200/256)

__global__ __launch_bounds__(256, 1)
void interaction_kernel(const float* __restrict__ rbf,
                        const int*   __restrict__ nmask,
                        const float* __restrict__ W1,
                        const float* __restrict__ b1,
                        const float* __restrict__ W2,
                        const float* __restrict__ b2,
                        const float* __restrict__ Wo1,
                        const float* __restrict__ bo1,
                        const float* __restrict__ Wo2,
                        const float* __restrict__ bo2,
                        const float* __restrict__ features,
                        float*       __restrict__ out) {
    extern __shared__ float smem[];
    float* W1s   = smem + OFF_W1;
    float* W2s   = smem + OFF_W2;
    float* rbf_s = smem + OFF_RBF;
    float* h_s   = smem + OFF_H;
    float* fw_s  = smem + OFF_FW;
    float* red   = smem + OFF_RED;

    const int bi   = blockIdx.x;          // b*N + i
    const int b    = bi / N_;
    const int tid  = threadIdx.x;
    const int warp = tid >> 5;

    // ---- stage weights as tf32; zero-pad W1 rows 50..63; zero rbf_s ----
    for (int idx = tid; idx < 64 * F_; idx += 256) {
        const int g = idx >> 7;
        const int f = idx & 127;
        W1s[g * LDW + f] = (g < G_) ? to_tf32(W1[g * F_ + f]) : 0.0f;
    }
    for (int idx = tid; idx < F_ * F_; idx += 256) {
        const int k = idx >> 7;
        const int f = idx & 127;
        W2s[k * LDW + f] = to_tf32(W2[idx]);
    }
    for (int idx = tid; idx < JT * LDR; idx += 256) rbf_s[idx] = 0.0f;

    const float* rbf_base  = rbf + (size_t)bi * N_ * G_;
    const int*   mask_base = nmask + (size_t)bi * N_;

    const int f_e  = tid & 127;
    const int half = tid >> 7;
    const float b1r = b1[f_e];
    const float b2r = b2[f_e];
    float agg = 0.0f;

    // warp tile: 2 m-tiles x 2 n-tiles of 16x16
    const int mt = (warp >> 2) * 32;      // 0 or 32
    const int nt = (warp & 3) * 32;       // 0,32,64,96

    // ---- prefetch tile 0 (contiguous: JT rows x 50 cols) ----
    float pre[PRE_N];
#pragma unroll
    for (int i = 0; i < PRE_N; ++i) {
        const int e = tid + i * 256;
        pre[i] = (e < TILE_ELEMS) ? rbf_base[e] : 0.0f;
    }

    for (int t = 0; t < NT; ++t) {
        __syncthreads();   // rbf_s / fw_s / red consumers from prev iter done

        // ---- commit prefetched tile to smem (tf32) + mask cache ----
#pragma unroll
        for (int i = 0; i < PRE_N; ++i) {
            const int e = tid + i * 256;
            if (e < TILE_ELEMS) {
                const int r = (e * 1311) >> 16;      // e / 50
                const int c = e - r * G_;
                rbf_s[r * LDR + c] = to_tf32(pre[i]);
            }
        }
        if (tid < JT) red[tid] = (float)mask_base[t * JT + tid];
        __syncthreads();

        // ---- prefetch next tile (overlaps GEMMs) ----
        if (t + 1 < NT) {
            const float* p = rbf_base + (size_t)(t + 1) * TILE_ELEMS;
#pragma unroll
            for (int i = 0; i < PRE_N; ++i) {
                const int e = tid + i * 256;
                pre[i] = (e < TILE_ELEMS) ? p[e] : 0.0f;
            }
        }

        // ---- GEMM1: [JT,64] @ [64,128] -> h_s (pre-activation) ----
        {
            wmma::fragment<wmma::accumulator, 16, 16, 8, float> c00, c01, c10, c11;
            wmma::fill_fragment(c00, 0.0f);
            wmma::fill_fragment(c01, 0.0f);
            wmma::fill_fragment(c10, 0.0f);
            wmma::fill_fragment(c11, 0.0f);
#pragma unroll
            for (int k = 0; k < 64; k += 8) {
                wmma::fragment<wmma::matrix_a, 16, 16, 8, wmma::precision::tf32, wmma::row_major> a0, a1;
                wmma::fragment<wmma::matrix_b, 16, 16, 8, wmma::precision::tf32, wmma::row_major> bb0, bb1;
                wmma::load_matrix_sync(a0, rbf_s + (mt + 0) * LDR + k, LDR);
                wmma::load_matrix_sync(a1, rbf_s + (mt + 16) * LDR + k, LDR);
                wmma::load_matrix_sync(bb0, W1s + k * LDW + nt, LDW);
                wmma::load_matrix_sync(bb1, W1s + k * LDW + nt + 16, LDW);
                wmma::mma_sync(c00, a0, bb0, c00);
                wmma::mma_sync(c01, a0, bb1, c01);
                wmma::mma_sync(c10, a1, bb0, c10);
                wmma::mma_sync(c11, a1, bb1, c11);
            }
            wmma::store_matrix_sync(h_s + (mt + 0) * LDW + nt,       c00, LDW, wmma::mem_row_major);
            wmma::store_matrix_sync(h_s + (mt + 0) * LDW + nt + 16,  c01, LDW, wmma::mem_row_major);
            wmma::store_matrix_sync(h_s + (mt + 16) * LDW + nt,      c10, LDW, wmma::mem_row_major);
            wmma::store_matrix_sync(h_s + (mt + 16) * LDW + nt + 16, c11, LDW, wmma::mem_row_major);
        }
        __syncthreads();

        // ---- softplus(+b1) in place, convert to tf32 for GEMM2 ----
        {
#pragma unroll
            for (int i = 0; i < JT / 2; ++i) {
                const int r = half + i * 2;
                const int e = r * LDW + f_e;
                h_s[e] = to_tf32(softplus_fast(h_s[e] + b1r));
            }
        }
        __syncthreads();

        // ---- GEMM2: [JT,128] @ [128,128] -> fw_s ----
        {
            wmma::fragment<wmma::accumulator, 16, 16, 8, float> c00, c01, c10, c11;
            wmma::fill_fragment(c00, 0.0f);
            wmma::fill_fragment(c01, 0.0f);
            wmma::fill_fragment(c10, 0.0f);
            wmma::fill_fragment(c11, 0.0f);
#pragma unroll
            for (int k = 0; k < 128; k += 8) {
                wmma::fragment<wmma::matrix_a, 16, 16, 8, wmma::precision::tf32, wmma::row_major> a0, a1;
                wmma::fragment<wmma::matrix_b, 16, 16, 8, wmma::precision::tf32, wmma::row_major> bb0, bb1;
                wmma::load_matrix_sync(a0, h_s + (mt + 0) * LDW + k, LDW);
                wmma::load_matrix_sync(a1, h_s + (mt + 16) * LDW + k, LDW);
                wmma::load_matrix_sync(bb0, W2s + k * LDW + nt, LDW);
                wmma::load_matrix_sync(bb1, W2s + k * LDW + nt + 16, LDW);
                wmma::mma_sync(c00, a0, bb0, c00);
                wmma::mma_sync(c01, a0, bb1, c01);
                wmma::mma_sync(c10, a1, bb0, c10);
                wmma::mma_sync(c11, a1, bb1, c11);
            }
            wmma::store_matrix_sync(fw_s + (mt + 0) * LDW + nt,       c00, LDW, wmma::mem_row_major);
            wmma::store_matrix_sync(fw_s + (mt + 0) * LDW + nt + 16,  c01, LDW, wmma::mem_row_major);
            wmma::store_matrix_sync(fw_s + (mt + 16) * LDW + nt,      c10, LDW, wmma::mem_row_major);
            wmma::store_matrix_sync(fw_s + (mt + 16) * LDW + nt + 16, c11, LDW, wmma::mem_row_major);
        }
        __syncthreads();

        // ---- masked elementwise multiply with nf, accumulate over j ----
        {
            const float* nf_p = g_nf + ((size_t)(b * N_ + t * JT + half)) * F_ + f_e;
#pragma unroll 8
            for (int jj = half; jj < JT; jj += 2) {
                const float m = red[jj];
                const float fw = fw_s[jj * LDW + f_e] + b2r;
                agg = fmaf(fw * m, nf_p[(size_t)(jj - half) * F_], agg);
            }
        }
    }

    // ---- reduce the two halves ----
    __syncthreads();
    red[tid] = agg;
    __syncthreads();
    if (tid < 128) {
        h_s[tid] = red[tid] + red[tid + 128];   // agg vector
    }
    __syncthreads();

    // ---- output MLP: softplus(agg @ Wo1 + bo1) @ Wo2 + bo2 + residual ----
    float t1 = 0.0f;
    if (tid < 128) {
        t1 = bo1[tid];
#pragma unroll 8
        for (int f = 0; f < F_; ++f) {
            t1 = fmaf(h_s[f], Wo1[f * H_ + tid], t1);
        }
        t1 = softplus_fast(t1);
    }
    __syncthreads();
    if (tid < 128) fw_s[tid] = t1;
    __syncthreads();
    if (tid < 128) {
        float o = bo2[tid];
#pragma unroll 8
        for (int f = 0; f < F_; ++f) {
            o = fmaf(fw_s[f], Wo2[f * H_ + tid], o);
        }
        out[(size_t)bi * H_ + tid] = o + features[(size_t)bi * H_ + tid];
    }
}

// ---------------------------------------------------------------------------
extern "C" void kernel_launch(void* const* d_in, const int* in_sizes, int n_in,
                              void* d_out, int out_size) {
    const float* features = (const float*)d_in[0];
    const float* rbf      = (const float*)d_in[1];
    const int*   nmask    = (const int*)  d_in[2];
    const float* W_rbf1   = (const float*)d_in[3];
    const float* b_rbf1   = (const float*)d_in[4];
    const float* W_rbf2   = (const float*)d_in[5];
    const float* b_rbf2   = (const float*)d_in[6];
    const float* W_f      = (const float*)d_in[7];
    const float* b_f      = (const float*)d_in[8];
    const float* W_o1     = (const float*)d_in[9];
    const float* b_o1     = (const float*)d_in[10];
    const float* W_o2     = (const float*)d_in[11];
    const float* b_o2     = (const float*)d_in[12];
    float* out = (float*)d_out;

    const int smem_bytes = SMEM_FLOATS * sizeof(float);
    static int configured = -1;
    if (configured < 0) {
        cudaFuncSetAttribute(interaction_kernel,
                             cudaFuncAttributeMaxDynamicSharedMemorySize, smem_bytes);
        configured = 1;
    }

    nf_kernel<<<B_ * N_, 128>>>(features, W_f, b_f);
    interaction_kernel<<<B_ * N_, 256, smem_bytes>>>(
        rbf, nmask, W_rbf1, b_rbf1, W_rbf2, b_rbf2,
        W_o1, b_o1, W_o2, b_o2, features, out);
}

// round 3
// speedup vs baseline: 2.2479x; 1.1878x over previous
#include <cuda_runtime.h>
#include <mma.h>

using namespace nvcuda;

#define B_  16
#define N_  192
#define H_  128
#define F_  128
#define G_  50
#define KP  56      // G padded to multiple of 8
#define JT  32      // neighbor tile rows
#define NT  6       // N_/JT
#define NG  3       // atom groups per CTA

#define LDW 132     // padded row stride for 128-wide tiles

// scratch: nf = features @ W_f + b_f  [B*N, F]
__device__ float g_nf[B_ * N_ * F_];

__device__ __forceinline__ float softplus_fast(float x) {
    float ax = fabsf(x);
    return fmaxf(x, 0.0f) + __logf(1.0f + __expf(-ax));
}
__device__ __forceinline__ float to_tf32(float x) { return wmma::__float_to_tf32(x); }

__device__ __forceinline__ void gbar(int id, int cnt) {
    asm volatile("bar.sync %0, %1;" :: "r"(id), "r"(cnt) : "memory");
}

// ---------------------------------------------------------------------------
// Kernel 1: nf[b*N+j, f] = features[b,j,:] @ W_f + b_f
// ---------------------------------------------------------------------------
__global__ __launch_bounds__(128)
void nf_kernel(const float* __restrict__ features,
               const float* __restrict__ W_f,
               const float* __restrict__ b_f) {
    __shared__ float fs[H_];
    const int row = blockIdx.x;
    const int f   = threadIdx.x;
    fs[f] = features[(size_t)row * H_ + f];
    __syncthreads();
    float acc = b_f[f];
#pragma unroll 8
    for (int h = 0; h < H_; ++h) acc = fmaf(fs[h], W_f[h * F_ + f], acc);
    g_nf[(size_t)row * F_ + f] = acc;
}

// ---------------------------------------------------------------------------
// Kernel 2: 3 atoms per CTA, 768 threads (3 groups x 8 warps).
// SMEM (floats):
//   W1s [KP][LDW]  (shared, tf32, rows 50..55 zero)
//   W2s [128][LDW] (shared, tf32)
//   per group: rbffw[JT][LDW] (rbf cols 0..55, later fw cols 0..127)
//              h    [JT][LDW]
//              red  [256]
// ---------------------------------------------------------------------------
#define OFF_W1  0
#define OFF_W2  (OFF_W1 + KP * LDW)
#define OFF_G   (OFF_W2 + 128 * LDW)
#define GSZ     (JT * LDW * 2 + 256)
#define SMEM_FLOATS (OFF_G + NG * GSZ)

__global__ __launch_bounds__(768, 1)
void interaction_kernel(const float* __restrict__ rbf,
                        const int*   __restrict__ nmask,
                        const float* __restrict__ W1,
                        const float* __restrict__ b1,
                        const float* __restrict__ W2,
                        const float* __restrict__ b2,
                        const float* __restrict__ Wo1,
                        const float* __restrict__ bo1,
                        const float* __restrict__ Wo2,
                        const float* __restrict__ bo2,
                        const float* __restrict__ features,
                        float*       __restrict__ out) {
    extern __shared__ float smem[];
    float* W1s = smem + OFF_W1;
    float* W2s = smem + OFF_W2;

    const int tid  = threadIdx.x;
    const int g    = tid >> 8;            // group 0..2
    const int gtid = tid & 255;           // thread within group
    const int wg   = gtid >> 5;           // warp within group 0..7
    const int lane = tid & 31;

    float* rbffw = smem + OFF_G + g * GSZ;           // [JT][LDW]
    float* h_s   = rbffw + JT * LDW;                 // [JT][LDW]
    float* red   = h_s + JT * LDW;                   // [256]

    const int bi = blockIdx.x * NG + g;   // atom index b*N + i
    const int b  = bi / N_;

    // ---- stage shared weights (tf32), zero-pad W1 rows 50..55 ----
    for (int idx = tid; idx < KP * F_; idx += 768) {
        const int k = idx >> 7;
        const int f = idx & 127;
        W1s[k * LDW + f] = (k < G_) ? to_tf32(W1[k * F_ + f]) : 0.0f;
    }
    for (int idx = tid; idx < F_ * F_; idx += 768) {
        const int k = idx >> 7;
        const int f = idx & 127;
        W2s[k * LDW + f] = to_tf32(W2[idx]);
    }

    const float* rbf_base  = rbf + (size_t)bi * N_ * G_;
    const int*   mask_base = nmask + (size_t)bi * N_;

    // warp tile: 1 m-tile (16 rows) x 2 n-tiles (32 cols)
    const int mt = (wg >> 2) * 16;        // 0 or 16
    const int nt = (wg & 3) * 32;         // 0,32,64,96

    // per-thread constants
    const float b1c = b1[nt + lane];      // column owned in softplus phase
    const int   f_e = gtid & 127;
    const int   half = gtid >> 7;
    const float b2r = b2[f_e];
    float agg = 0.0f;

    __syncthreads();

    for (int t = 0; t < NT; ++t) {
        gbar(g + 1, 256);   // prev iteration's fw/red fully consumed

        // ---- commit rbf tile [JT][0..55], zero pad cols 50..55 ----
        for (int idx = gtid; idx < JT * KP; idx += 256) {
            const int r = idx / KP;
            const int c = idx % KP;
            rbffw[r * LDW + c] = (c < G_) ? to_tf32(rbf_base[(size_t)(t * JT + r) * G_ + c]) : 0.0f;
        }
        if (gtid < JT) red[gtid] = (float)mask_base[t * JT + gtid];
        gbar(g + 1, 256);

        // ---- GEMM1: [JT,KP] @ [KP,128] -> h_s ----
        {
            wmma::fragment<wmma::accumulator, 16, 16, 8, float> c0, c1;
            wmma::fill_fragment(c0, 0.0f);
            wmma::fill_fragment(c1, 0.0f);
#pragma unroll
            for (int k = 0; k < KP; k += 8) {
                wmma::fragment<wmma::matrix_a, 16, 16, 8, wmma::precision::tf32, wmma::row_major> a;
                wmma::fragment<wmma::matrix_b, 16, 16, 8, wmma::precision::tf32, wmma::row_major> bb0, bb1;
                wmma::load_matrix_sync(a, rbffw + mt * LDW + k, LDW);
                wmma::load_matrix_sync(bb0, W1s + k * LDW + nt, LDW);
                wmma::load_matrix_sync(bb1, W1s + k * LDW + nt + 16, LDW);
                wmma::mma_sync(c0, a, bb0, c0);
                wmma::mma_sync(c1, a, bb1, c1);
            }
            wmma::store_matrix_sync(h_s + mt * LDW + nt,      c0, LDW, wmma::mem_row_major);
            wmma::store_matrix_sync(h_s + mt * LDW + nt + 16, c1, LDW, wmma::mem_row_major);
        }
        __syncwarp();

        // ---- softplus(+b1) on own region: rows mt..mt+16, col nt+lane ----
#pragma unroll
        for (int i = 0; i < 16; ++i) {
            const int e = (mt + i) * LDW + nt + lane;
            h_s[e] = to_tf32(softplus_fast(h_s[e] + b1c));
        }
        gbar(g + 1, 256);

        // ---- GEMM2: [JT,128] @ [128,128] -> fw (overlays rbf region) ----
        {
            wmma::fragment<wmma::accumulator, 16, 16, 8, float> c0, c1;
            wmma::fill_fragment(c0, 0.0f);
            wmma::fill_fragment(c1, 0.0f);
#pragma unroll
            for (int k = 0; k < F_; k += 8) {
                wmma::fragment<wmma::matrix_a, 16, 16, 8, wmma::precision::tf32, wmma::row_major> a;
                wmma::fragment<wmma::matrix_b, 16, 16, 8, wmma::precision::tf32, wmma::row_major> bb0, bb1;
                wmma::load_matrix_sync(a, h_s + mt * LDW + k, LDW);
                wmma::load_matrix_sync(bb0, W2s + k * LDW + nt, LDW);
                wmma::load_matrix_sync(bb1, W2s + k * LDW + nt + 16, LDW);
                wmma::mma_sync(c0, a, bb0, c0);
                wmma::mma_sync(c1, a, bb1, c1);
            }
            wmma::store_matrix_sync(rbffw + mt * LDW + nt,      c0, LDW, wmma::mem_row_major);
            wmma::store_matrix_sync(rbffw + mt * LDW + nt + 16, c1, LDW, wmma::mem_row_major);
        }
        gbar(g + 1, 256);

        // ---- masked elementwise multiply with nf, accumulate over j ----
        {
            const float* nf_p = g_nf + ((size_t)(b * N_ + t * JT + half)) * F_ + f_e;
#pragma unroll
            for (int jj = half; jj < JT; jj += 2) {
                const float m  = red[jj];
                const float fw = rbffw[jj * LDW + f_e] + b2r;
                agg = fmaf(fw * m, nf_p[(size_t)(jj - half) * F_], agg);
            }
        }
    }

    // ---- reduce halves ----
    gbar(g + 1, 256);
    red[gtid] = agg;
    gbar(g + 1, 256);

    if (gtid < 128) {
        h_s[gtid] = red[gtid] + red[gtid + 128];   // agg vector
        gbar(g + 4, 128);

        // ---- output MLP + residual ----
        float t1 = bo1[gtid];
#pragma unroll 8
        for (int f = 0; f < F_; ++f) t1 = fmaf(h_s[f], Wo1[f * H_ + gtid], t1);
        t1 = softplus_fast(t1);
        rbffw[gtid] = t1;
        gbar(g + 4, 128);

        float o = bo2[gtid];
#pragma unroll 8
        for (int f = 0; f < F_; ++f) o = fmaf(rbffw[f], Wo2[f * H_ + gtid], o);
        out[(size_t)bi * H_ + gtid] = o + features[(size_t)bi * H_ + gtid];
    }
}

// ---------------------------------------------------------------------------
extern "C" void kernel_launch(void* const* d_in, const int* in_sizes, int n_in,
                              void* d_out, int out_size) {
    const float* features = (const float*)d_in[0];
    const float* rbf      = (const float*)d_in[1];
    const int*   nmask    = (const int*)  d_in[2];
    const float* W_rbf1   = (const float*)d_in[3];
    const float* b_rbf1   = (const float*)d_in[4];
    const float* W_rbf2   = (const float*)d_in[5];
    const float* b_rbf2   = (const float*)d_in[6];
    const float* W_f      = (const float*)d_in[7];
    const float* b_f      = (const float*)d_in[8];
    const float* W_o1     = (const float*)d_in[9];
    const float* b_o1     = (const float*)d_in[10];
    const float* W_o2     = (const float*)d_in[11];
    const float* b_o2     = (const float*)d_in[12];
    float* out = (float*)d_out;

    const int smem_bytes = SMEM_FLOATS * sizeof(float);
    static int configured = -1;
    if (configured < 0) {
        cudaFuncSetAttribute(interaction_kernel,
                             cudaFuncAttributeMaxDynamicSharedMemorySize, smem_bytes);
        configured = 1;
    }

    nf_kernel<<<B_ * N_, 128>>>(features, W_f, b_f);
    interaction_kernel<<<(B_ * N_) / NG, 768, smem_bytes>>>(
        rbf, nmask, W_rbf1, b_rbf1, W_rbf2, b_rbf2,
        W_o1, b_o1, W_o2, b_o2, features, out);
}

// round 5
// speedup vs baseline: 2.5264x; 1.1239x over previous
#include <cuda_runtime.h>
#include <mma.h>

using namespace nvcuda;

#define B_  16
#define N_  192
#define H_  128
#define F_  128
#define G_  50
#define KP  56      // GEMM1 K (50 rbf + bias row at 50 + 5 zero)
#define K2  136     // GEMM2 K (128 + bias row at 128 + 7 zero)
#define JT  32      // neighbor tile rows
#define NT  6       // N_/JT
#define NG  3       // atom groups per CTA

#define LDW 132     // row stride for 128-wide tiles (W1s/W2s/fw)
#define LDH 140     // row stride for h tile (136 cols)

// scratch: nf = features @ W_f + b_f  [B*N, F]
__device__ float g_nf[B_ * N_ * F_];

__device__ __forceinline__ float softplus_fast(float x) {
    float ax = fabsf(x);
    return fmaxf(x, 0.0f) + __logf(1.0f + __expf(-ax));
}
__device__ __forceinline__ float to_tf32(float x) { return wmma::__float_to_tf32(x); }

__device__ __forceinline__ void gbar(int id, int cnt) {
    asm volatile("bar.sync %0, %1;" :: "r"(id), "r"(cnt) : "memory");
}

// ---------------------------------------------------------------------------
// Kernel 1: nf[b*N+j, f] = features[b,j,:] @ W_f + b_f
// ---------------------------------------------------------------------------
__global__ __launch_bounds__(128)
void nf_kernel(const float* __restrict__ features,
               const float* __restrict__ W_f,
               const float* __restrict__ b_f) {
    __shared__ float fs[H_];
    const int row = blockIdx.x;
    const int f   = threadIdx.x;
    fs[f] = features[(size_t)row * H_ + f];
    __syncthreads();
    float acc = b_f[f];
#pragma unroll 8
    for (int h = 0; h < H_; ++h) acc = fmaf(fs[h], W_f[h * F_ + f], acc);
    g_nf[(size_t)row * F_ + f] = acc;
}

// ---------------------------------------------------------------------------
// Kernel 2: 3 atoms per CTA, 768 threads (3 groups x 8 warps).
// SMEM (floats):
//   W1s [KP][LDW]  shared tf32; row 50 = b1, rows 51..55 = 0
//   W2s [K2][LDW]  shared tf32; row 128 = b2, rows 129..135 = 0
//   per group: rbffw [JT][LDW]  (rbf cols 0..55 incl bias-1 col; later fw 0..127)
//              h     [JT][LDH]  (col 128 = 1.0, 129..135 = 0, set once)
//              red   [256]      (mask cache [32] during loop, reduction after)
// ---------------------------------------------------------------------------
#define OFF_W1  0
#define OFF_W2  (OFF_W1 + KP * LDW)
#define OFF_G   (OFF_W2 + K2 * LDW)
#define GSZ     (JT * LDW + JT * LDH + 256)
#define SMEM_FLOATS (OFF_G + NG * GSZ)

#define TILE_ELEMS (JT * G_)   // 1600
#define PRE_N 7                // ceil(1600/256)

__global__ __launch_bounds__(768, 1)
void interaction_kernel(const float* __restrict__ rbf,
                        const int*   __restrict__ nmask,
                        const float* __restrict__ W1,
                        const float* __restrict__ b1,
                        const float* __restrict__ W2,
                        const float* __restrict__ b2,
                        const float* __restrict__ Wo1,
                        const float* __restrict__ bo1,
                        const float* __restrict__ Wo2,
                        const float* __restrict__ bo2,
                        const float* __restrict__ features,
                        float*       __restrict__ out) {
    extern __shared__ float smem[];
    float* W1s = smem + OFF_W1;
    float* W2s = smem + OFF_W2;

    const int tid  = threadIdx.x;
    const int g    = tid >> 8;            // group 0..2
    const int gtid = tid & 255;           // thread within group
    const int wg   = gtid >> 5;           // warp within group 0..7

    float* rbffw = smem + OFF_G + g * GSZ;           // [JT][LDW]
    float* h_s   = rbffw + JT * LDW;                 // [JT][LDH]
    float* red   = h_s + JT * LDH;                   // [256]

    const int bi = blockIdx.x * NG + g;   // atom index b*N + i
    const int b  = bi / N_;

    // ---- stage shared weights (tf32) with bias rows folded in ----
    for (int idx = tid; idx < KP * F_; idx += 768) {
        const int k = idx >> 7;
        const int f = idx & 127;
        float v = 0.0f;
        if (k < G_)       v = W1[k * F_ + f];
        else if (k == G_) v = b1[f];
        W1s[k * LDW + f] = to_tf32(v);
    }
    for (int idx = tid; idx < K2 * F_; idx += 768) {
        const int k = idx >> 7;
        const int f = idx & 127;
        float v = 0.0f;
        if (k < 128)       v = W2[k * F_ + f];
        else if (k == 128) v = b2[f];
        W2s[k * LDW + f] = to_tf32(v);
    }
    // ---- h bias columns (written once; GEMM1 stores only cols < 128) ----
    for (int idx = gtid; idx < JT * 8; idx += 256) {
        const int r = idx >> 3;
        const int c = 128 + (idx & 7);
        h_s[r * LDH + c] = (c == 128) ? 1.0f : 0.0f;
    }

    const float* rbf_base  = rbf + (size_t)bi * N_ * G_;
    const int*   mask_base = nmask + (size_t)bi * N_;

    // warp tile: 1 m-tile (16 rows) x 2 n-tiles (32 cols)
    const int mt = (wg >> 2) * 16;        // 0 or 16
    const int nt = (wg & 3) * 32;         // 0,32,64,96

    const int   f_e  = gtid & 127;
    const int   half = gtid >> 7;
    float agg = 0.0f;

    // ---- prefetch tile 0 ----
    float pre[PRE_N];
#pragma unroll
    for (int i = 0; i < PRE_N; ++i) {
        const int e = gtid + i * 256;
        pre[i] = (e < TILE_ELEMS) ? rbf_base[e] : 0.0f;
    }

    __syncthreads();

    for (int t = 0; t < NT; ++t) {
        gbar(g + 1, 256);   // prev iteration's fw/red fully consumed

        // ---- commit rbf tile [JT][0..49] (tf32) + bias col 50 + zeros ----
#pragma unroll
        for (int i = 0; i < PRE_N; ++i) {
            const int e = gtid + i * 256;
            if (e < TILE_ELEMS) {
                const int r = (e * 1311) >> 16;     // e / 50
                const int c = e - r * G_;
                rbffw[r * LDW + c] = to_tf32(pre[i]);
            }
        }
        if (gtid < JT * 6) {
            const int r = gtid / 6;
            const int c = G_ + gtid - r * 6;
            rbffw[r * LDW + c] = (c == G_) ? 1.0f : 0.0f;
        }
        if (gtid < JT) red[gtid] = (float)mask_base[t * JT + gtid];
        gbar(g + 1, 256);

        // ---- prefetch next tile (overlaps GEMMs) ----
        if (t + 1 < NT) {
            const float* p = rbf_base + (size_t)(t + 1) * TILE_ELEMS;
#pragma unroll
            for (int i = 0; i < PRE_N; ++i) {
                const int e = gtid + i * 256;
                pre[i] = (e < TILE_ELEMS) ? p[e] : 0.0f;
            }
        }

        // ---- GEMM1: [JT,KP] @ [KP,128] -> softplus in-reg -> h_s ----
        {
            wmma::fragment<wmma::accumulator, 16, 16, 8, float> c0, c1;
            wmma::fill_fragment(c0, 0.0f);
            wmma::fill_fragment(c1, 0.0f);
#pragma unroll
            for (int k = 0; k < KP; k += 8) {
                wmma::fragment<wmma::matrix_a, 16, 16, 8, wmma::precision::tf32, wmma::row_major> a;
                wmma::fragment<wmma::matrix_b, 16, 16, 8, wmma::precision::tf32, wmma::row_major> bb0, bb1;
                wmma::load_matrix_sync(a, rbffw + mt * LDW + k, LDW);
                wmma::load_matrix_sync(bb0, W1s + k * LDW + nt, LDW);
                wmma::load_matrix_sync(bb1, W1s + k * LDW + nt + 16, LDW);
                wmma::mma_sync(c0, a, bb0, c0);
                wmma::mma_sync(c1, a, bb1, c1);
            }
#pragma unroll
            for (int i = 0; i < c0.num_elements; ++i) c0.x[i] = to_tf32(softplus_fast(c0.x[i]));
#pragma unroll
            for (int i = 0; i < c1.num_elements; ++i) c1.x[i] = to_tf32(softplus_fast(c1.x[i]));
            wmma::store_matrix_sync(h_s + mt * LDH + nt,      c0, LDH, wmma::mem_row_major);
            wmma::store_matrix_sync(h_s + mt * LDH + nt + 16, c1, LDH, wmma::mem_row_major);
        }
        gbar(g + 1, 256);

        // ---- GEMM2: [JT,K2] @ [K2,128] -> fw (overlays rbf region) ----
        {
            wmma::fragment<wmma::accumulator, 16, 16, 8, float> c0, c1;
            wmma::fill_fragment(c0, 0.0f);
            wmma::fill_fragment(c1, 0.0f);
#pragma unroll
            for (int k = 0; k < K2; k += 8) {
                wmma::fragment<wmma::matrix_a, 16, 16, 8, wmma::precision::tf32, wmma::row_major> a;
                wmma::fragment<wmma::matrix_b, 16, 16, 8, wmma::precision::tf32, wmma::row_major> bb0, bb1;
                wmma::load_matrix_sync(a, h_s + mt * LDH + k, LDH);
                wmma::load_matrix_sync(bb0, W2s + k * LDW + nt, LDW);
                wmma::load_matrix_sync(bb1, W2s + k * LDW + nt + 16, LDW);
                wmma::mma_sync(c0, a, bb0, c0);
                wmma::mma_sync(c1, a, bb1, c1);
            }
            wmma::store_matrix_sync(rbffw + mt * LDW + nt,      c0, LDW, wmma::mem_row_major);
            wmma::store_matrix_sync(rbffw + mt * LDW + nt + 16, c1, LDW, wmma::mem_row_major);
        }
        gbar(g + 1, 256);

        // ---- masked elementwise multiply with nf, accumulate over j ----
        {
            const float* nf_p = g_nf + ((size_t)(b * N_ + t * JT + half)) * F_ + f_e;
#pragma unroll
            for (int jj = half; jj < JT; jj += 2) {
                const float m  = red[jj];
                const float fw = rbffw[jj * LDW + f_e];
                agg = fmaf(fw * m, nf_p[(size_t)(jj - half) * F_], agg);
            }
        }
    }

    // ---- reduce halves ----
    gbar(g + 1, 256);
    red[gtid] = agg;
    gbar(g + 1, 256);

    if (gtid < 128) {
        h_s[gtid] = red[gtid] + red[gtid + 128];   // agg vector
        gbar(g + 4, 128);

        // ---- output MLP + residual ----
        float t1 = bo1[gtid];
#pragma unroll 8
        for (int f = 0; f < F_; ++f) t1 = fmaf(h_s[f], Wo1[f * H_ + gtid], t1);
        t1 = softplus_fast(t1);
        rbffw[gtid] = t1;
        gbar(g + 4, 128);

        float o = bo2[gtid];
#pragma unroll 8
        for (int f = 0; f < F_; ++f) o = fmaf(rbffw[f], Wo2[f * H_ + gtid], o);
        out[(size_t)bi * H_ + gtid] = o + features[(size_t)bi * H_ + gtid];
    }
}

// ---------------------------------------------------------------------------
extern "C" void kernel_launch(void* const* d_in, const int* in_sizes, int n_in,
                              void* d_out, int out_size) {
    const float* features = (const float*)d_in[0];
    const float* rbf      = (const float*)d_in[1];
    const int*   nmask    = (const int*)  d_in[2];
    const float* W_rbf1   = (const float*)d_in[3];
    const float* b_rbf1   = (const float*)d_in[4];
    const float* W_rbf2   = (const float*)d_in[5];
    const float* b_rbf2   = (const float*)d_in[6];
    const float* W_f      = (const float*)d_in[7];
    const float* b_f      = (const float*)d_in[8];
    const float* W_o1     = (const float*)d_in[9];
    const float* b_o1     = (const float*)d_in[10];
    const float* W_o2     = (const float*)d_in[11];
    const float* b_o2     = (const float*)d_in[12];
    float* out = (float*)d_out;

    const int smem_bytes = SMEM_FLOATS * sizeof(float);
    static int configured = -1;
    if (configured < 0) {
        cudaFuncSetAttribute(interaction_kernel,
                             cudaFuncAttributeMaxDynamicSharedMemorySize, smem_bytes);
        configured = 1;
    }

    nf_kernel<<<B_ * N_, 128>>>(features, W_f, b_f);
    interaction_kernel<<<(B_ * N_) / NG, 768, smem_bytes>>>(
        rbf, nmask, W_rbf1, b_rbf1, W_rbf2, b_rbf2,
        W_o1, b_o1, W_o2, b_o2, features, out);
}

// round 7
// speedup vs baseline: 5.6901x; 2.2523x over previous
#include <cuda_runtime.h>
#include <cuda_fp16.h>
#include <cstdint>

#define B_  16
#define N_  192
#define H_  128
#define F_  128
#define G_  50
#define JT  64      // j rows per tile
#define NTL 3       // tiles per atom (192/64)
#define NG  3       // atom groups per CTA
#define K1  64      // GEMM1 K (50 + bias row 50 + zeros)
#define K2  144     // GEMM2 K (128 + bias row 128 + zeros)

#define LDA1 72     // rbf tile stride (halfs)
#define LDB  136    // weight tile stride (halfs)
#define LDH2 152    // h tile stride (halfs)

// byte offsets in dynamic smem
#define W1_OFF   0
#define W2_OFF   (64 * LDB * 2)                 // 17408
#define GRP_OFF  (W2_OFF + K2 * LDB * 2)        // 56576
#define RBF_OFF  0
#define H_OFF    (JT * LDA1 * 2)                // 9216
#define MASK_OFF (H_OFF + JT * LDH2 * 2)        // 28672
#define RED_OFF  (MASK_OFF + JT * 4)            // 28928
#define GRP_BYTES (RED_OFF + 256 * 4)           // 29952
#define SMEM_BYTES (GRP_OFF + NG * GRP_BYTES)   // 146432

__device__ float g_nf[B_ * N_ * F_];

__device__ __forceinline__ float softplus_fast(float x) {
    float ax = fabsf(x);
    return fmaxf(x, 0.0f) + __logf(1.0f + __expf(-ax));
}
__device__ __forceinline__ void gbar(int id, int cnt) {
    asm volatile("bar.sync %0, %1;" :: "r"(id), "r"(cnt) : "memory");
}

#define LDSM4(R, ADDR) \
    asm volatile("ldmatrix.sync.aligned.m8n8.x4.shared.b16 {%0,%1,%2,%3}, [%4];" \
        : "=r"((R)[0]), "=r"((R)[1]), "=r"((R)[2]), "=r"((R)[3]) : "r"(ADDR))
#define LDSM4T(R, ADDR) \
    asm volatile("ldmatrix.sync.aligned.m8n8.x4.trans.shared.b16 {%0,%1,%2,%3}, [%4];" \
        : "=r"((R)[0]), "=r"((R)[1]), "=r"((R)[2]), "=r"((R)[3]) : "r"(ADDR))
#define MMA16816(C, A, B0, B1) \
    asm volatile("mma.sync.aligned.m16n8k16.row.col.f32.f16.f16.f32 " \
        "{%0,%1,%2,%3}, {%4,%5,%6,%7}, {%8,%9}, {%0,%1,%2,%3};" \
        : "+f"((C)[0]), "+f"((C)[1]), "+f"((C)[2]), "+f"((C)[3]) \
        : "r"((A)[0]), "r"((A)[1]), "r"((A)[2]), "r"((A)[3]), "r"(B0), "r"(B1))

// ---------------------------------------------------------------------------
__global__ __launch_bounds__(128)
void nf_kernel(const float* __restrict__ features,
               const float* __restrict__ W_f,
               const float* __restrict__ b_f) {
    __shared__ float fs[H_];
    const int row = blockIdx.x;
    const int f   = threadIdx.x;
    fs[f] = features[(size_t)row * H_ + f];
    __syncthreads();
    float acc = b_f[f];
#pragma unroll 8
    for (int h = 0; h < H_; ++h) acc = fmaf(fs[h], W_f[h * F_ + f], acc);
    g_nf[(size_t)row * F_ + f] = acc;
}

// ---------------------------------------------------------------------------
__global__ __launch_bounds__(768, 1)
void interaction_kernel(const float* __restrict__ rbf,
                        const int*   __restrict__ nmask,
                        const float* __restrict__ W1,
                        const float* __restrict__ b1,
                        const float* __restrict__ W2,
                        const float* __restrict__ b2,
                        const float* __restrict__ Wo1,
                        const float* __restrict__ bo1,
                        const float* __restrict__ Wo2,
                        const float* __restrict__ bo2,
                        const float* __restrict__ features,
                        float*       __restrict__ out) {
    extern __shared__ char smem[];
    const uint32_t sb = (uint32_t)__cvta_generic_to_shared(smem);

    const int tid  = threadIdx.x;
    const int g    = tid >> 8;
    const int gtid = tid & 255;
    const int wg   = gtid >> 5;
    const int lane = tid & 31;

    __half* W1h = (__half*)(smem + W1_OFF);
    __half* W2h = (__half*)(smem + W2_OFF);
    char*   gsm = smem + GRP_OFF + g * GRP_BYTES;
    __half* rbh = (__half*)(gsm + RBF_OFF);
    __half* hh  = (__half*)(gsm + H_OFF);
    float*  mask_s = (float*)(gsm + MASK_OFF);
    float*  redf   = (float*)(gsm + RED_OFF);

    const int bi = blockIdx.x * NG + g;     // atom = b*N + i
    const int b  = bi / N_;

    // ---- stage weights (fp16) with bias rows folded ----
    for (int idx = tid; idx < K1 * F_; idx += 768) {
        const int k = idx >> 7, n = idx & 127;
        float v = 0.0f;
        if (k < G_)       v = W1[k * F_ + n];
        else if (k == G_) v = b1[n];
        W1h[k * LDB + n] = __float2half_rn(v);
    }
    for (int idx = tid; idx < K2 * F_; idx += 768) {
        const int k = idx >> 7, n = idx & 127;
        float v = 0.0f;
        if (k < 128)       v = W2[k * F_ + n];
        else if (k == 128) v = b2[n];
        W2h[k * LDB + n] = __float2half_rn(v);
    }
    // rbf tile constant cols 50..71 (bias=1 at 50, zeros beyond), once
    for (int idx = gtid; idx < JT * 22; idx += 256) {
        const int r = idx / 22, c = G_ + idx - (idx / 22) * 22;
        rbh[r * LDA1 + c] = (c == G_) ? __float2half_rn(1.0f) : __float2half_rn(0.0f);
    }
    // h tile constant cols 128..151 (bias=1 at 128), once
    for (int idx = gtid; idx < JT * 24; idx += 256) {
        const int r = idx / 24, c = 128 + idx - (idx / 24) * 24;
        hh[r * LDH2 + c] = (c == 128) ? __float2half_rn(1.0f) : __float2half_rn(0.0f);
    }

    const float* rbf_base  = rbf + (size_t)bi * N_ * G_;
    const int*   mask_base = nmask + (size_t)bi * N_;
    const float* nf_b      = g_nf + (size_t)b * N_ * F_;

    const int mt = (wg >> 2) * 32;      // 0 / 32
    const int nt = (wg & 3) * 32;       // 0 / 32 / 64 / 96
    const int qrow = lane >> 2;
    const int qcol = (lane & 3) * 2;

    // ldmatrix base addresses (per-lane)
    const int arow = lane & 15;
    const int asel = (lane >> 4) * 8;
    const uint32_t aA1 = sb + (uint32_t)(gsm - smem) + RBF_OFF + ((mt + arow) * LDA1 + asel) * 2;
    const uint32_t aA2 = sb + (uint32_t)(gsm - smem) + H_OFF   + ((mt + arow) * LDH2 + asel) * 2;
    const uint32_t aB1 = sb + W1_OFF + (arow * LDB + nt + asel) * 2;
    const uint32_t aB2 = sb + W2_OFF + (arow * LDB + nt + asel) * 2;

    float agg[4][2] = {{0.f,0.f},{0.f,0.f},{0.f,0.f},{0.f,0.f}};

    __syncthreads();

    for (int t = 0; t < NTL; ++t) {
        gbar(g + 1, 256);   // prev tile fully consumed

        // ---- load rbf tile [64 x 50] -> fp16 smem; mask ----
        {
            const float* rt = rbf_base + (size_t)t * (JT * G_);
            for (int idx = gtid; idx < JT * G_; idx += 256) {
                const int r = (idx * 1311) >> 16;   // idx / 50
                const int c = idx - r * G_;
                rbh[r * LDA1 + c] = __float2half_rn(rt[idx]);
            }
            if (gtid < JT) mask_s[gtid] = (float)mask_base[t * JT + gtid];
        }
        gbar(g + 1, 256);

        // ---- GEMM1: [64,K1]@[K1,128] -> softplus -> h (fp16) ----
        {
            float c1[2][4][4];
#pragma unroll
            for (int mi = 0; mi < 2; ++mi)
#pragma unroll
                for (int ni = 0; ni < 4; ++ni)
#pragma unroll
                    for (int e = 0; e < 4; ++e) c1[mi][ni][e] = 0.0f;

#pragma unroll
            for (int ks = 0; ks < K1 / 16; ++ks) {
                uint32_t a[2][4], bb[2][4];
                LDSM4(a[0], aA1 + ks * 32);
                LDSM4(a[1], aA1 + 16 * LDA1 * 2 + ks * 32);
                LDSM4T(bb[0], aB1 + ks * 16 * LDB * 2);
                LDSM4T(bb[1], aB1 + 32 + ks * 16 * LDB * 2);
#pragma unroll
                for (int mi = 0; mi < 2; ++mi)
#pragma unroll
                    for (int ni = 0; ni < 4; ++ni)
                        MMA16816(c1[mi][ni], a[mi], bb[ni >> 1][(ni & 1) * 2], bb[ni >> 1][(ni & 1) * 2 + 1]);
            }
            // softplus + pack half2 + store to h
#pragma unroll
            for (int mi = 0; mi < 2; ++mi) {
                const int r0 = mt + mi * 16 + qrow;
#pragma unroll
                for (int ni = 0; ni < 4; ++ni) {
                    const int cc = nt + ni * 8 + qcol;
                    __half2 lo = __floats2half2_rn(softplus_fast(c1[mi][ni][0]),
                                                   softplus_fast(c1[mi][ni][1]));
                    __half2 hi = __floats2half2_rn(softplus_fast(c1[mi][ni][2]),
                                                   softplus_fast(c1[mi][ni][3]));
                    *(__half2*)(gsm + H_OFF + (r0 * LDH2 + cc) * 2)       = lo;
                    *(__half2*)(gsm + H_OFF + ((r0 + 8) * LDH2 + cc) * 2) = hi;
                }
            }
        }
        gbar(g + 1, 256);

        // ---- GEMM2: [64,K2]@[K2,128] -> masked nf aggregation in regs ----
        {
            float c2[2][4][4];
#pragma unroll
            for (int mi = 0; mi < 2; ++mi)
#pragma unroll
                for (int ni = 0; ni < 4; ++ni)
#pragma unroll
                    for (int e = 0; e < 4; ++e) c2[mi][ni][e] = 0.0f;

#pragma unroll
            for (int ks = 0; ks < K2 / 16; ++ks) {
                uint32_t a[2][4], bb[2][4];
                LDSM4(a[0], aA2 + ks * 32);
                LDSM4(a[1], aA2 + 16 * LDH2 * 2 + ks * 32);
                LDSM4T(bb[0], aB2 + ks * 16 * LDB * 2);
                LDSM4T(bb[1], aB2 + 32 + ks * 16 * LDB * 2);
#pragma unroll
                for (int mi = 0; mi < 2; ++mi)
#pragma unroll
                    for (int ni = 0; ni < 4; ++ni)
                        MMA16816(c2[mi][ni], a[mi], bb[ni >> 1][(ni & 1) * 2], bb[ni >> 1][(ni & 1) * 2 + 1]);
            }
            // aggregate: agg[f] += fw * mask[j] * nf[j,f]
#pragma unroll
            for (int mi = 0; mi < 2; ++mi) {
                const int jl = mt + mi * 16 + qrow;
                const float m0 = mask_s[jl];
                const float m1 = mask_s[jl + 8];
                const float* nr0 = nf_b + (size_t)(t * JT + jl) * F_;
                const float* nr1 = nr0 + 8 * F_;
#pragma unroll
                for (int ni = 0; ni < 4; ++ni) {
                    const int cc = nt + ni * 8 + qcol;
                    const float2 v0 = *(const float2*)(nr0 + cc);
                    const float2 v1 = *(const float2*)(nr1 + cc);
                    agg[ni][0] = fmaf(c2[mi][ni][0] * m0, v0.x, agg[ni][0]);
                    agg[ni][1] = fmaf(c2[mi][ni][1] * m0, v0.y, agg[ni][1]);
                    agg[ni][0] = fmaf(c2[mi][ni][2] * m1, v1.x, agg[ni][0]);
                    agg[ni][1] = fmaf(c2[mi][ni][3] * m1, v1.y, agg[ni][1]);
                }
            }
        }
    }

    // ---- cross-lane reduction of agg (rows within warp) ----
#pragma unroll
    for (int ni = 0; ni < 4; ++ni)
#pragma unroll
        for (int p = 0; p < 2; ++p) {
            float v = agg[ni][p];
            v += __shfl_xor_sync(0xffffffffu, v, 4);
            v += __shfl_xor_sync(0xffffffffu, v, 8);
            v += __shfl_xor_sync(0xffffffffu, v, 16);
            agg[ni][p] = v;
        }
    if (lane < 4) {
#pragma unroll
        for (int ni = 0; ni < 4; ++ni)
#pragma unroll
            for (int p = 0; p < 2; ++p)
                redf[(wg >> 2) * 128 + nt + ni * 8 + lane * 2 + p] = agg[ni][p];
    }
    gbar(g + 1, 256);

    // ---- output MLP + residual (128 threads per group) ----
    if (gtid < 128) {
        float* sc  = (float*)(gsm + RBF_OFF);        // rbf region is dead
        float* sc2 = sc + 128;
        sc[gtid] = redf[gtid] + redf[128 + gtid];
        gbar(g + 4, 128);

        float t1 = bo1[gtid];
#pragma unroll 8
        for (int f = 0; f < F_; ++f) t1 = fmaf(sc[f], Wo1[f * H_ + gtid], t1);
        t1 = softplus_fast(t1);
        sc2[gtid] = t1;
        gbar(g + 4, 128);

        float o = bo2[gtid];
#pragma unroll 8
        for (int f = 0; f < F_; ++f) o = fmaf(sc2[f], Wo2[f * H_ + gtid], o);
        out[(size_t)bi * H_ + gtid] = o + features[(size_t)bi * H_ + gtid];
    }
}

// ---------------------------------------------------------------------------
extern "C" void kernel_launch(void* const* d_in, const int* in_sizes, int n_in,
                              void* d_out, int out_size) {
    const float* features = (const float*)d_in[0];
    const float* rbf      = (const float*)d_in[1];
    const int*   nmask    = (const int*)  d_in[2];
    const float* W_rbf1   = (const float*)d_in[3];
    const float* b_rbf1   = (const float*)d_in[4];
    const float* W_rbf2   = (const float*)d_in[5];
    const float* b_rbf2   = (const float*)d_in[6];
    const float* W_f      = (const float*)d_in[7];
    const float* b_f      = (const float*)d_in[8];
    const float* W_o1     = (const float*)d_in[9];
    const float* b_o1     = (const float*)d_in[10];
    const float* W_o2     = (const float*)d_in[11];
    const float* b_o2     = (const float*)d_in[12];
    float* out = (float*)d_out;

    static int configured = -1;
    if (configured < 0) {
        cudaFuncSetAttribute(interaction_kernel,
                             cudaFuncAttributeMaxDynamicSharedMemorySize, SMEM_BYTES);
        configured = 1;
    }

    nf_kernel<<<B_ * N_, 128>>>(features, W_f, b_f);
    interaction_kernel<<<(B_ * N_) / NG, 768, SMEM_BYTES>>>(
        rbf, nmask, W_rbf1, b_rbf1, W_rbf2, b_rbf2,
        W_o1, b_o1, W_o2, b_o2, features, out);
}

// round 8
// speedup vs baseline: 6.7793x; 1.1914x over previous
#include <cuda_runtime.h>
#include <cuda_fp16.h>
#include <cstdint>

#define B_  16
#define N_  192
#define H_  128
#define F_  128
#define G_  50
#define JT  64      // j rows per tile
#define NG  3       // atom groups per CTA
#define K1  64      // GEMM1 K (50 + bias row 50 + zeros)
#define K2  144     // GEMM2 K (128 + bias row 128 + zeros)

#define LDA1 72     // rbf tile stride (halfs)
#define LDB  136    // weight tile stride (halfs)
#define LDH2 152    // h tile stride (halfs)

// byte offsets in dynamic smem
#define W1_OFF   0
#define W2_OFF   (64 * LDB * 2)                 // 17408
#define GRP_OFF  (W2_OFF + K2 * LDB * 2)        // 56576
#define RBF_OFF  0
#define H_OFF    (JT * LDA1 * 2)                // 9216
#define WT_OFF   (H_OFF + JT * LDH2 * 2)        // 28672
#define RED_OFF  (WT_OFF + JT * 4)              // 28928
#define JL_OFF   (RED_OFF + 256 * 4)            // 29952
#define JR_OFF   (JL_OFF + 192 * 4)             // 30720
#define CNT_OFF  (JR_OFF + JT * 4)              // 30976
#define GRP_BYTES (CNT_OFF + 32)                // 31008
#define SMEM_BYTES (GRP_OFF + NG * GRP_BYTES)   // 149600

__device__ float g_nf[B_ * N_ * F_];

__device__ __forceinline__ float softplus_fast(float x) {
    float ax = fabsf(x);
    return fmaxf(x, 0.0f) + __logf(1.0f + __expf(-ax));
}
__device__ __forceinline__ void gbar(int id, int cnt) {
    asm volatile("bar.sync %0, %1;" :: "r"(id), "r"(cnt) : "memory");
}

#define LDSM4(R, ADDR) \
    asm volatile("ldmatrix.sync.aligned.m8n8.x4.shared.b16 {%0,%1,%2,%3}, [%4];" \
        : "=r"((R)[0]), "=r"((R)[1]), "=r"((R)[2]), "=r"((R)[3]) : "r"(ADDR))
#define LDSM4T(R, ADDR) \
    asm volatile("ldmatrix.sync.aligned.m8n8.x4.trans.shared.b16 {%0,%1,%2,%3}, [%4];" \
        : "=r"((R)[0]), "=r"((R)[1]), "=r"((R)[2]), "=r"((R)[3]) : "r"(ADDR))
#define MMA16816(C, A, B0, B1) \
    asm volatile("mma.sync.aligned.m16n8k16.row.col.f32.f16.f16.f32 " \
        "{%0,%1,%2,%3}, {%4,%5,%6,%7}, {%8,%9}, {%0,%1,%2,%3};" \
        : "+f"((C)[0]), "+f"((C)[1]), "+f"((C)[2]), "+f"((C)[3]) \
        : "r"((A)[0]), "r"((A)[1]), "r"((A)[2]), "r"((A)[3]), "r"(B0), "r"(B1))

// ---------------------------------------------------------------------------
__global__ __launch_bounds__(128)
void nf_kernel(const float* __restrict__ features,
               const float* __restrict__ W_f,
               const float* __restrict__ b_f) {
    __shared__ float fs[H_];
    const int row = blockIdx.x;
    const int f   = threadIdx.x;
    fs[f] = features[(size_t)row * H_ + f];
    __syncthreads();
    float acc = b_f[f];
#pragma unroll 8
    for (int h = 0; h < H_; ++h) acc = fmaf(fs[h], W_f[h * F_ + f], acc);
    g_nf[(size_t)row * F_ + f] = acc;
}

// ---------------------------------------------------------------------------
__global__ __launch_bounds__(768, 1)
void interaction_kernel(const float* __restrict__ rbf,
                        const int*   __restrict__ nmask,
                        const float* __restrict__ W1,
                        const float* __restrict__ b1,
                        const float* __restrict__ W2,
                        const float* __restrict__ b2,
                        const float* __restrict__ Wo1,
                        const float* __restrict__ bo1,
                        const float* __restrict__ Wo2,
                        const float* __restrict__ bo2,
                        const float* __restrict__ features,
                        float*       __restrict__ out) {
    extern __shared__ char smem[];
    const uint32_t sb = (uint32_t)__cvta_generic_to_shared(smem);

    const int tid  = threadIdx.x;
    const int g    = tid >> 8;
    const int gtid = tid & 255;
    const int wg   = gtid >> 5;
    const int lane = tid & 31;

    __half* W1h = (__half*)(smem + W1_OFF);
    __half* W2h = (__half*)(smem + W2_OFF);
    char*   gsm = smem + GRP_OFF + g * GRP_BYTES;
    __half* rbh = (__half*)(gsm + RBF_OFF);
    __half* hh  = (__half*)(gsm + H_OFF);
    float*  wt_s  = (float*)(gsm + WT_OFF);
    float*  redf  = (float*)(gsm + RED_OFF);
    int*    jl_s  = (int*)(gsm + JL_OFF);
    int*    jr_s  = (int*)(gsm + JR_OFF);
    int*    cnt_s = (int*)(gsm + CNT_OFF);

    const int bi = blockIdx.x * NG + g;     // atom = b*N + i
    const int b  = bi / N_;

    // ---- stage weights (fp16) with bias rows folded ----
    for (int idx = tid; idx < K1 * F_; idx += 768) {
        const int k = idx >> 7, n = idx & 127;
        float v = 0.0f;
        if (k < G_)       v = W1[k * F_ + n];
        else if (k == G_) v = b1[n];
        W1h[k * LDB + n] = __float2half_rn(v);
    }
    for (int idx = tid; idx < K2 * F_; idx += 768) {
        const int k = idx >> 7, n = idx & 127;
        float v = 0.0f;
        if (k < 128)       v = W2[k * F_ + n];
        else if (k == 128) v = b2[n];
        W2h[k * LDB + n] = __float2half_rn(v);
    }
    // rbf tile constant cols 50..71 (bias=1 at 50, zeros beyond), once
    for (int idx = gtid; idx < JT * 22; idx += 256) {
        const int r = idx / 22, c = G_ + idx - (idx / 22) * 22;
        rbh[r * LDA1 + c] = (c == G_) ? __float2half_rn(1.0f) : __float2half_rn(0.0f);
    }
    // h tile constant cols 128..151 (bias=1 at 128), once
    for (int idx = gtid; idx < JT * 24; idx += 256) {
        const int r = idx / 24, c = 128 + idx - (idx / 24) * 24;
        hh[r * LDH2 + c] = (c == 128) ? __float2half_rn(1.0f) : __float2half_rn(0.0f);
    }

    const float* rbf_base  = rbf + (size_t)bi * N_ * G_;
    const int*   mask_base = nmask + (size_t)bi * N_;
    const float* nf_b      = g_nf + (size_t)b * N_ * F_;

    // ---- mask compaction: jl_s[0..cnt) = indices j with mask==1 ----
    {
        int* iscr = (int*)redf;    // 8 ints scratch (redf unused until epilogue)
        const int m = (gtid < N_) ? mask_base[gtid] : 0;
        int v = m;
#pragma unroll
        for (int o = 1; o < 32; o <<= 1) {
            int nv = __shfl_up_sync(0xffffffffu, v, o);
            if (lane >= o) v += nv;
        }
        if (lane == 31) iscr[wg] = v;
        gbar(g + 1, 256);
        int base = 0;
        for (int w = 0; w < wg; ++w) base += iscr[w];
        if (gtid < N_ && m) jl_s[base + v - m] = gtid;
        if (gtid == 0) {
            int c = 0;
#pragma unroll
            for (int w = 0; w < 8; ++w) c += iscr[w];
            cnt_s[0] = c;
        }
        gbar(g + 1, 256);
    }
    const int cnt    = cnt_s[0];
    const int ntiles = (cnt + JT - 1) >> 6;

    const int mt = (wg >> 2) * 32;      // 0 / 32
    const int nt = (wg & 3) * 32;       // 0 / 32 / 64 / 96
    const int qrow = lane >> 2;
    const int qcol = (lane & 3) * 2;

    // ldmatrix base addresses (per-lane)
    const int arow = lane & 15;
    const int asel = (lane >> 4) * 8;
    const uint32_t aA1 = sb + (uint32_t)(gsm - smem) + RBF_OFF + ((mt + arow) * LDA1 + asel) * 2;
    const uint32_t aA2 = sb + (uint32_t)(gsm - smem) + H_OFF   + ((mt + arow) * LDH2 + asel) * 2;
    const uint32_t aB1 = sb + W1_OFF + (arow * LDB + nt + asel) * 2;
    const uint32_t aB2 = sb + W2_OFF + (arow * LDB + nt + asel) * 2;

    float agg[4][2] = {{0.f,0.f},{0.f,0.f},{0.f,0.f},{0.f,0.f}};

    __syncthreads();

    for (int t = 0; t < ntiles; ++t) {
        gbar(g + 1, 256);   // prev tile fully consumed (wt/jr/rbh reuse)

        // ---- gather compacted rbf rows [64 x 50] -> fp16 smem ----
        for (int idx = gtid; idx < JT * G_; idx += 256) {
            const int r = (idx * 1311) >> 16;   // idx / 50
            const int c = idx - r * G_;
            const int rowpos = t * JT + r;
            float v = 0.0f;
            if (rowpos < cnt) v = rbf_base[(size_t)jl_s[rowpos] * G_ + c];
            rbh[r * LDA1 + c] = __float2half_rn(v);
        }
        if (gtid < JT) {
            const int rowpos = t * JT + gtid;
            const bool ok = rowpos < cnt;
            wt_s[gtid] = ok ? 1.0f : 0.0f;
            jr_s[gtid] = ok ? jl_s[rowpos] : 0;
        }
        gbar(g + 1, 256);

        // ---- GEMM1: [64,K1]@[K1,128] -> softplus -> h (fp16) ----
        {
            float c1[2][4][4];
#pragma unroll
            for (int mi = 0; mi < 2; ++mi)
#pragma unroll
                for (int ni = 0; ni < 4; ++ni)
#pragma unroll
                    for (int e = 0; e < 4; ++e) c1[mi][ni][e] = 0.0f;

#pragma unroll
            for (int ks = 0; ks < K1 / 16; ++ks) {
                uint32_t a[2][4], bb[2][4];
                LDSM4(a[0], aA1 + ks * 32);
                LDSM4(a[1], aA1 + 16 * LDA1 * 2 + ks * 32);
                LDSM4T(bb[0], aB1 + ks * 16 * LDB * 2);
                LDSM4T(bb[1], aB1 + 32 + ks * 16 * LDB * 2);
#pragma unroll
                for (int mi = 0; mi < 2; ++mi)
#pragma unroll
                    for (int ni = 0; ni < 4; ++ni)
                        MMA16816(c1[mi][ni], a[mi], bb[ni >> 1][(ni & 1) * 2], bb[ni >> 1][(ni & 1) * 2 + 1]);
            }
#pragma unroll
            for (int mi = 0; mi < 2; ++mi) {
                const int r0 = mt + mi * 16 + qrow;
#pragma unroll
                for (int ni = 0; ni < 4; ++ni) {
                    const int cc = nt + ni * 8 + qcol;
                    __half2 lo = __floats2half2_rn(softplus_fast(c1[mi][ni][0]),
                                                   softplus_fast(c1[mi][ni][1]));
                    __half2 hi = __floats2half2_rn(softplus_fast(c1[mi][ni][2]),
                                                   softplus_fast(c1[mi][ni][3]));
                    *(__half2*)(gsm + H_OFF + (r0 * LDH2 + cc) * 2)       = lo;
                    *(__half2*)(gsm + H_OFF + ((r0 + 8) * LDH2 + cc) * 2) = hi;
                }
            }
        }
        gbar(g + 1, 256);

        // ---- GEMM2: [64,K2]@[K2,128] -> weighted nf aggregation in regs ----
        {
            float c2[2][4][4];
#pragma unroll
            for (int mi = 0; mi < 2; ++mi)
#pragma unroll
                for (int ni = 0; ni < 4; ++ni)
#pragma unroll
                    for (int e = 0; e < 4; ++e) c2[mi][ni][e] = 0.0f;

#pragma unroll
            for (int ks = 0; ks < K2 / 16; ++ks) {
                uint32_t a[2][4], bb[2][4];
                LDSM4(a[0], aA2 + ks * 32);
                LDSM4(a[1], aA2 + 16 * LDH2 * 2 + ks * 32);
                LDSM4T(bb[0], aB2 + ks * 16 * LDB * 2);
                LDSM4T(bb[1], aB2 + 32 + ks * 16 * LDB * 2);
#pragma unroll
                for (int mi = 0; mi < 2; ++mi)
#pragma unroll
                    for (int ni = 0; ni < 4; ++ni)
                        MMA16816(c2[mi][ni], a[mi], bb[ni >> 1][(ni & 1) * 2], bb[ni >> 1][(ni & 1) * 2 + 1]);
            }
#pragma unroll
            for (int mi = 0; mi < 2; ++mi) {
                const int jl = mt + mi * 16 + qrow;
                const float m0 = wt_s[jl];
                const float m1 = wt_s[jl + 8];
                const float* nr0 = nf_b + (size_t)jr_s[jl] * F_;
                const float* nr1 = nf_b + (size_t)jr_s[jl + 8] * F_;
#pragma unroll
                for (int ni = 0; ni < 4; ++ni) {
                    const int cc = nt + ni * 8 + qcol;
                    const float2 v0 = *(const float2*)(nr0 + cc);
                    const float2 v1 = *(const float2*)(nr1 + cc);
                    agg[ni][0] = fmaf(c2[mi][ni][0] * m0, v0.x, agg[ni][0]);
                    agg[ni][1] = fmaf(c2[mi][ni][1] * m0, v0.y, agg[ni][1]);
                    agg[ni][0] = fmaf(c2[mi][ni][2] * m1, v1.x, agg[ni][0]);
                    agg[ni][1] = fmaf(c2[mi][ni][3] * m1, v1.y, agg[ni][1]);
                }
            }
        }
    }

    // ---- cross-lane reduction of agg ----
#pragma unroll
    for (int ni = 0; ni < 4; ++ni)
#pragma unroll
        for (int p = 0; p < 2; ++p) {
            float v = agg[ni][p];
            v += __shfl_xor_sync(0xffffffffu, v, 4);
            v += __shfl_xor_sync(0xffffffffu, v, 8);
            v += __shfl_xor_sync(0xffffffffu, v, 16);
            agg[ni][p] = v;
        }
    gbar(g + 1, 256);   // ensure compaction scratch in redf is dead
    if (lane < 4) {
#pragma unroll
        for (int ni = 0; ni < 4; ++ni)
#pragma unroll
            for (int p = 0; p < 2; ++p)
                redf[(wg >> 2) * 128 + nt + ni * 8 + lane * 2 + p] = agg[ni][p];
    }
    gbar(g + 1, 256);

    // ---- output MLP + residual (128 threads per group) ----
    if (gtid < 128) {
        float* sc  = (float*)(gsm + RBF_OFF);        // rbf region is dead
        float* sc2 = sc + 128;
        sc[gtid] = redf[gtid] + redf[128 + gtid];
        gbar(g + 4, 128);

        float t1 = bo1[gtid];
#pragma unroll 8
        for (int f = 0; f < F_; ++f) t1 = fmaf(sc[f], Wo1[f * H_ + gtid], t1);
        t1 = softplus_fast(t1);
        sc2[gtid] = t1;
        gbar(g + 4, 128);

        float o = bo2[gtid];
#pragma unroll 8
        for (int f = 0; f < F_; ++f) o = fmaf(sc2[f], Wo2[f * H_ + gtid], o);
        out[(size_t)bi * H_ + gtid] = o + features[(size_t)bi * H_ + gtid];
    }
}

// ---------------------------------------------------------------------------
extern "C" void kernel_launch(void* const* d_in, const int* in_sizes, int n_in,
                              void* d_out, int out_size) {
    const float* features = (const float*)d_in[0];
    const float* rbf      = (const float*)d_in[1];
    const int*   nmask    = (const int*)  d_in[2];
    const float* W_rbf1   = (const float*)d_in[3];
    const float* b_rbf1   = (const float*)d_in[4];
    const float* W_rbf2   = (const float*)d_in[5];
    const float* b_rbf2   = (const float*)d_in[6];
    const float* W_f      = (const float*)d_in[7];
    const float* b_f      = (const float*)d_in[8];
    const float* W_o1     = (const float*)d_in[9];
    const float* b_o1     = (const float*)d_in[10];
    const float* W_o2     = (const float*)d_in[11];
    const float* b_o2     = (const float*)d_in[12];
    float* out = (float*)d_out;

    static int configured = -1;
    if (configured < 0) {
        cudaFuncSetAttribute(interaction_kernel,
                             cudaFuncAttributeMaxDynamicSharedMemorySize, SMEM_BYTES);
        configured = 1;
    }

    nf_kernel<<<B_ * N_, 128>>>(features, W_f, b_f);
    interaction_kernel<<<(B_ * N_) / NG, 768, SMEM_BYTES>>>(
        rbf, nmask, W_rbf1, b_rbf1, W_rbf2, b_rbf2,
        W_o1, b_o1, W_o2, b_o2, features, out);
}

// round 11
// speedup vs baseline: 7.2089x; 1.0634x over previous
#include <cuda_runtime.h>
#include <cuda_fp16.h>
#include <cstdint>

#define B_  16
#define N_  192
#define H_  128
#define F_  128
#define G_  50
#define NG  3       // atom groups per CTA (256 threads each)
#define TM  128     // tile rows (8 warps x 16)
#define LDA1 72     // rbh row stride (halfs), conflict-free for ldmatrix
#define LDB  136    // weight row stride (halfs)

// group byte offsets
#define RBF_OFF 0                       // 128*72*2 = 18432 (also epilogue scratch)
#define WT_OFF  18432                   // 128 floats
#define JR_OFF  18944                   // 128 ints
#define JL_OFF  19456                   // 192 ints
#define RED_OFF 20224                   // 8*128 floats = 4096
#define B1_OFF  24320                   // 128 floats
#define B2_OFF  24832                   // 128 floats
#define CNT_OFF 25344                   // cnt + 8-int scan scratch
#define GRP_BYTES 25408

#define W1_OFF 0                        // 64*136*2  = 17408
#define W2_OFF 17408                    // 128*136*2 = 34816
#define GRP0_OFF 52224
#define SMEM_BYTES (GRP0_OFF + NG * GRP_BYTES)   // 128448

__device__ float g_nf[B_ * N_ * F_];

__device__ __forceinline__ float softplus_fast(float x) {
    float ax = fabsf(x);
    return fmaxf(x, 0.0f) + __logf(1.0f + __expf(-ax));
}
__device__ __forceinline__ void gbar(int id, int cnt) {
    asm volatile("bar.sync %0, %1;" :: "r"(id), "r"(cnt) : "memory");
}
__device__ __forceinline__ uint32_t packh2(float a, float b) {
    __half2 h = __floats2half2_rn(a, b);
    return *reinterpret_cast<uint32_t*>(&h);
}

#define LDSM4(R, ADDR) \
    asm volatile("ldmatrix.sync.aligned.m8n8.x4.shared.b16 {%0,%1,%2,%3}, [%4];" \
        : "=r"((R)[0]), "=r"((R)[1]), "=r"((R)[2]), "=r"((R)[3]) : "r"(ADDR))
#define LDSM4T(R, ADDR) \
    asm volatile("ldmatrix.sync.aligned.m8n8.x4.trans.shared.b16 {%0,%1,%2,%3}, [%4];" \
        : "=r"((R)[0]), "=r"((R)[1]), "=r"((R)[2]), "=r"((R)[3]) : "r"(ADDR))
#define MMA16816(C, A, B0, B1) \
    asm volatile("mma.sync.aligned.m16n8k16.row.col.f32.f16.f16.f32 " \
        "{%0,%1,%2,%3}, {%4,%5,%6,%7}, {%8,%9}, {%0,%1,%2,%3};" \
        : "+f"((C)[0]), "+f"((C)[1]), "+f"((C)[2]), "+f"((C)[3]) \
        : "r"((A)[0]), "r"((A)[1]), "r"((A)[2]), "r"((A)[3]), "r"(B0), "r"(B1))

// ---------------------------------------------------------------------------
__global__ __launch_bounds__(128)
void nf_kernel(const float* __restrict__ features,
               const float* __restrict__ W_f,
               const float* __restrict__ b_f) {
    __shared__ float fs[H_];
    const int row = blockIdx.x;
    const int f   = threadIdx.x;
    fs[f] = features[(size_t)row * H_ + f];
    __syncthreads();
    float acc = b_f[f];
#pragma unroll 8
    for (int h = 0; h < H_; ++h) acc = fmaf(fs[h], W_f[h * F_ + f], acc);
    g_nf[(size_t)row * F_ + f] = acc;
}

// ---------------------------------------------------------------------------
__global__ __launch_bounds__(768, 1)
void interaction_kernel(const float* __restrict__ rbf,
                        const int*   __restrict__ nmask,
                        const float* __restrict__ W1,
                        const float* __restrict__ b1,
                        const float* __restrict__ W2,
                        const float* __restrict__ b2,
                        const float* __restrict__ Wo1,
                        const float* __restrict__ bo1,
                        const float* __restrict__ Wo2,
                        const float* __restrict__ bo2,
                        const float* __restrict__ features,
                        float*       __restrict__ out) {
    extern __shared__ char smem[];
    const uint32_t sb = (uint32_t)__cvta_generic_to_shared(smem);

    const int tid  = threadIdx.x;
    const int g    = tid >> 8;
    const int gtid = tid & 255;
    const int wg   = gtid >> 5;          // warp in group 0..7
    const int lane = tid & 31;

    __half* W1h = (__half*)(smem + W1_OFF);
    __half* W2h = (__half*)(smem + W2_OFF);
    char*   gsm = smem + GRP0_OFF + g * GRP_BYTES;
    __half* rbh   = (__half*)(gsm + RBF_OFF);
    float*  wt_s  = (float*)(gsm + WT_OFF);
    int*    jr_s  = (int*)(gsm + JR_OFF);
    int*    jl_s  = (int*)(gsm + JL_OFF);
    float*  red   = (float*)(gsm + RED_OFF);
    float*  b1_s  = (float*)(gsm + B1_OFF);
    float*  b2_s  = (float*)(gsm + B2_OFF);
    int*    cnt_s = (int*)(gsm + CNT_OFF);

    const int bi = blockIdx.x * NG + g;     // atom = b*N + i
    const int b  = bi / N_;

    // ---- stage weights fp16 (no bias rows; biases go to accumulator init) ----
    for (int idx = tid; idx < 64 * F_; idx += 768) {
        const int k = idx >> 7, n = idx & 127;
        W1h[k * LDB + n] = __float2half_rn((k < G_) ? W1[k * F_ + n] : 0.0f);
    }
    for (int idx = tid; idx < F_ * F_; idx += 768) {
        const int k = idx >> 7, n = idx & 127;
        W2h[k * LDB + n] = __float2half_rn(W2[idx]);
    }
    // per-group inits
    if (gtid < 128) { b1_s[gtid] = b1[gtid]; b2_s[gtid] = b2[gtid]; }
    for (int idx = gtid; idx < 8 * 128; idx += 256) red[idx] = 0.0f;
    // rbh pad cols 50..63 zero (gather never writes them)
    for (int idx = gtid; idx < TM * 14; idx += 256) {
        const int r = idx / 14, c = G_ + idx - (idx / 14) * 14;
        rbh[r * LDA1 + c] = __float2half_rn(0.0f);
    }

    const float* rbf_base  = rbf + (size_t)bi * N_ * G_;
    const int*   mask_base = nmask + (size_t)bi * N_;
    const float* nf_b      = g_nf + (size_t)b * N_ * F_;

    __syncthreads();

    // ---- mask compaction: jl_s[0..cnt) = j with mask==1 ----
    {
        int* iscr = cnt_s + 1;
        const int m = (gtid < N_) ? mask_base[gtid] : 0;
        int v = m;
#pragma unroll
        for (int o = 1; o < 32; o <<= 1) {
            int nv = __shfl_up_sync(0xffffffffu, v, o);
            if (lane >= o) v += nv;
        }
        if (lane == 31) iscr[wg] = v;
        gbar(g + 1, 256);
        int base = 0;
        for (int w = 0; w < wg; ++w) base += iscr[w];
        if (gtid < N_ && m) jl_s[base + v - m] = gtid;
        if (gtid == 0) {
            int c = 0;
#pragma unroll
            for (int w = 0; w < 8; ++w) c += iscr[w];
            cnt_s[0] = c;
        }
        gbar(g + 1, 256);
    }
    const int cnt    = cnt_s[0];
    const int ntiles = (cnt + TM - 1) >> 7;     // 1 in practice (2 if cnt>128)

    const int qrow = lane >> 2;
    const int qcol = (lane & 3) * 2;
    const int arow = lane & 15;
    const int asel = (lane >> 4) * 8;

    const uint32_t aA1 = sb + (uint32_t)(gsm - smem) + RBF_OFF
                       + ((wg * 16 + arow) * LDA1 + asel) * 2;
    const uint32_t aW1 = sb + W1_OFF + (arow * LDB + asel) * 2;
    const uint32_t aW2 = sb + W2_OFF + (arow * LDB + asel) * 2;

    for (int t = 0; t < ntiles; ++t) {
        if (t) gbar(g + 1, 256);   // rbh free before re-gather

        // ---- gather compacted rbf rows [128 x 50] -> fp16 ----
        for (int idx = gtid; idx < TM * G_; idx += 256) {
            const int r = (idx * 5243) >> 18;     // idx / 50
            const int c = idx - r * G_;
            const int rowpos = t * TM + r;
            float v = 0.0f;
            if (rowpos < cnt) v = rbf_base[(size_t)jl_s[rowpos] * G_ + c];
            rbh[r * LDA1 + c] = __float2half_rn(v);
        }
        if (gtid < TM) {
            const int rowpos = t * TM + gtid;
            const bool ok = rowpos < cnt;
            wt_s[gtid] = ok ? 1.0f : 0.0f;
            jr_s[gtid] = ok ? jl_s[rowpos] : 0;
        }
        gbar(g + 1, 256);

        // ---- per-warp 16-row strip; skip if fully dead ----
        if (t * TM + wg * 16 < cnt) {
            // GEMM1: [16,64]@[64,128] in two n-halves -> softplus -> A2 regs
            uint32_t A2[8][4];
#pragma unroll
            for (int h2 = 0; h2 < 2; ++h2) {
                float c1[8][4];
#pragma unroll
                for (int nb = 0; nb < 8; ++nb) {
                    const float2 bv = *(const float2*)(b1_s + h2 * 64 + nb * 8 + qcol);
                    c1[nb][0] = bv.x; c1[nb][1] = bv.y;
                    c1[nb][2] = bv.x; c1[nb][3] = bv.y;
                }
#pragma unroll
                for (int ks = 0; ks < 4; ++ks) {
                    uint32_t a[4];
                    LDSM4(a, aA1 + ks * 32);
#pragma unroll
                    for (int p = 0; p < 4; ++p) {
                        uint32_t bb[4];
                        LDSM4T(bb, aW1 + (ks * 16 * LDB + h2 * 64 + p * 16) * 2);
                        MMA16816(c1[p * 2],     a, bb[0], bb[1]);
                        MMA16816(c1[p * 2 + 1], a, bb[2], bb[3]);
                    }
                }
#pragma unroll
                for (int gk = 0; gk < 4; ++gk) {
                    A2[h2 * 4 + gk][0] = packh2(softplus_fast(c1[2 * gk][0]),
                                                softplus_fast(c1[2 * gk][1]));
                    A2[h2 * 4 + gk][1] = packh2(softplus_fast(c1[2 * gk][2]),
                                                softplus_fast(c1[2 * gk][3]));
                    A2[h2 * 4 + gk][2] = packh2(softplus_fast(c1[2 * gk + 1][0]),
                                                softplus_fast(c1[2 * gk + 1][1]));
                    A2[h2 * 4 + gk][3] = packh2(softplus_fast(c1[2 * gk + 1][2]),
                                                softplus_fast(c1[2 * gk + 1][3]));
                }
            }

            // GEMM2: [16,128]@[128,128] in 4 n-chunks, A from regs; fused agg
            const int r0 = wg * 16 + qrow;
            const float w0 = wt_s[r0];
            const float w1 = wt_s[r0 + 8];
            const float* nr0 = nf_b + (size_t)jr_s[r0] * F_;
            const float* nr1 = nf_b + (size_t)jr_s[r0 + 8] * F_;
            float* redw = red + wg * 128;

#pragma unroll
            for (int ch = 0; ch < 4; ++ch) {
                const int cc0 = ch * 32;
                float c2[4][4];
#pragma unroll
                for (int ni = 0; ni < 4; ++ni) {
                    const float2 bv = *(const float2*)(b2_s + cc0 + ni * 8 + qcol);
                    c2[ni][0] = bv.x; c2[ni][1] = bv.y;
                    c2[ni][2] = bv.x; c2[ni][3] = bv.y;
                }
#pragma unroll
                for (int ks = 0; ks < 8; ++ks) {
                    uint32_t bb0[4], bb1[4];
                    LDSM4T(bb0, aW2 + (ks * 16 * LDB + cc0) * 2);
                    LDSM4T(bb1, aW2 + (ks * 16 * LDB + cc0 + 16) * 2);
                    MMA16816(c2[0], A2[ks], bb0[0], bb0[1]);
                    MMA16816(c2[1], A2[ks], bb0[2], bb0[3]);
                    MMA16816(c2[2], A2[ks], bb1[0], bb1[1]);
                    MMA16816(c2[3], A2[ks], bb1[2], bb1[3]);
                }
#pragma unroll
                for (int ni = 0; ni < 4; ++ni) {
                    const int cc = cc0 + ni * 8 + qcol;
                    const float2 v0 = *(const float2*)(nr0 + cc);
                    const float2 v1 = *(const float2*)(nr1 + cc);
                    float s0 = c2[ni][0] * w0 * v0.x + c2[ni][2] * w1 * v1.x;
                    float s1 = c2[ni][1] * w0 * v0.y + c2[ni][3] * w1 * v1.y;
                    s0 += __shfl_xor_sync(0xffffffffu, s0, 4);
                    s0 += __shfl_xor_sync(0xffffffffu, s0, 8);
                    s0 += __shfl_xor_sync(0xffffffffu, s0, 16);
                    s1 += __shfl_xor_sync(0xffffffffu, s1, 4);
                    s1 += __shfl_xor_sync(0xffffffffu, s1, 8);
                    s1 += __shfl_xor_sync(0xffffffffu, s1, 16);
                    if (lane < 4) {
                        redw[cc]     += s0;
                        redw[cc + 1] += s1;
                    }
                }
            }
        }
    }

    gbar(g + 1, 256);

    // ---- final reduce + output MLP + residual (128 threads per group) ----
    if (gtid < 128) {
        float* sc  = (float*)(gsm + RBF_OFF);   // rbh region is dead
        float* sc2 = sc + 128;
        float a = 0.0f;
#pragma unroll
        for (int w = 0; w < 8; ++w) a += red[w * 128 + gtid];
        sc[gtid] = a;
        gbar(g + 4, 128);

        float t1 = bo1[gtid];
#pragma unroll 8
        for (int f = 0; f < F_; ++f) t1 = fmaf(sc[f], Wo1[f * H_ + gtid], t1);
        t1 = softplus_fast(t1);
        sc2[gtid] = t1;
        gbar(g + 4, 128);

        float o = bo2[gtid];
#pragma unroll 8
        for (int f = 0; f < F_; ++f) o = fmaf(sc2[f], Wo2[f * H_ + gtid], o);
        out[(size_t)bi * H_ + gtid] = o + features[(size_t)bi * H_ + gtid];
    }
}

// ---------------------------------------------------------------------------
extern "C" void kernel_launch(void* const* d_in, const int* in_sizes, int n_in,
                              void* d_out, int out_size) {
    const float* features = (const float*)d_in[0];
    const float* rbf      = (const float*)d_in[1];
    const int*   nmask    = (const int*)  d_in[2];
    const float* W_rbf1   = (const float*)d_in[3];
    const float* b_rbf1   = (const float*)d_in[4];
    const float* W_rbf2   = (const float*)d_in[5];
    const float* b_rbf2   = (const float*)d_in[6];
    const float* W_f      = (const float*)d_in[7];
    const float* b_f      = (const float*)d_in[8];
    const float* W_o1     = (const float*)d_in[9];
    const float* b_o1     = (const float*)d_in[10];
    const float* W_o2     = (const float*)d_in[11];
    const float* b_o2     = (const float*)d_in[12];
    float* out = (float*)d_out;

    static int configured = -1;
    if (configured < 0) {
        cudaFuncSetAttribute(interaction_kernel,
                             cudaFuncAttributeMaxDynamicSharedMemorySize, SMEM_BYTES);
        configured = 1;
    }

    nf_kernel<<<B_ * N_, 128>>>(features, W_f, b_f);
    interaction_kernel<<<(B_ * N_) / NG, 768, SMEM_BYTES>>>(
        rbf, nmask, W_rbf1, b_rbf1, W_rbf2, b_rbf2,
        W_o1, b_o1, W_o2, b_o2, features, out);
}

// round 14
// speedup vs baseline: 8.2240x; 1.1408x over previous
#include <cuda_runtime.h>
#include <cuda_fp16.h>
#include <cstdint>

#define B_  16
#define N_  192
#define H_  128
#define F_  128
#define G_  50
#define NG  3        // atom groups per CTA (256 threads each)
#define TM  128      // tile rows (8 warps x 16)
#define LDA1 72      // rbh row stride (halfs)
#define LDB  136     // weight row stride (halfs)
#define ATOMS (B_ * N_)
#define GRID 152
#define GSTRIDE (GRID * NG)   // 456

// group byte offsets
#define RBH_OFF 0                        // 128*72*2 = 18432
#define FST_OFF 18432                    // 128*50*4 = 25600 float staging
#define WT_OFF  44032                    // 128 floats
#define JR_OFF  44544                    // 128 ints
#define JL_OFF  45056                    // 2 x 192 ints
#define RED_OFF 46592                    // 8*128 floats
#define B1_OFF  50688                    // 128 floats
#define B2_OFF  51200                    // 128 floats
#define CNT_OFF 51712                    // cnt[2] + iscr[8]
#define SC_OFF  51776                    // 256 floats epilogue scratch
#define GRP_BYTES 52800

#define W1_OFF 0                         // 64*136*2  = 17408
#define W2_OFF 17408                     // 128*136*2 = 34816
#define GRP0_OFF 52224
#define SMEM_BYTES (GRP0_OFF + NG * GRP_BYTES)   // 210624

__device__ float g_nf[B_ * N_ * F_];

__device__ __forceinline__ float softplus_fast(float x) {
    float ax = fabsf(x);
    return fmaxf(x, 0.0f) + __logf(1.0f + __expf(-ax));
}
__device__ __forceinline__ void gbar(int id, int cnt) {
    asm volatile("bar.sync %0, %1;" :: "r"(id), "r"(cnt) : "memory");
}
__device__ __forceinline__ uint32_t packh2(float a, float b) {
    __half2 h = __floats2half2_rn(a, b);
    return *reinterpret_cast<uint32_t*>(&h);
}

#define LDSM4(R, ADDR) \
    asm volatile("ldmatrix.sync.aligned.m8n8.x4.shared.b16 {%0,%1,%2,%3}, [%4];" \
        : "=r"((R)[0]), "=r"((R)[1]), "=r"((R)[2]), "=r"((R)[3]) : "r"(ADDR))
#define LDSM4T(R, ADDR) \
    asm volatile("ldmatrix.sync.aligned.m8n8.x4.trans.shared.b16 {%0,%1,%2,%3}, [%4];" \
        : "=r"((R)[0]), "=r"((R)[1]), "=r"((R)[2]), "=r"((R)[3]) : "r"(ADDR))
#define MMA16816(C, A, B0, B1) \
    asm volatile("mma.sync.aligned.m16n8k16.row.col.f32.f16.f16.f32 " \
        "{%0,%1,%2,%3}, {%4,%5,%6,%7}, {%8,%9}, {%0,%1,%2,%3};" \
        : "+f"((C)[0]), "+f"((C)[1]), "+f"((C)[2]), "+f"((C)[3]) \
        : "r"((A)[0]), "r"((A)[1]), "r"((A)[2]), "r"((A)[3]), "r"(B0), "r"(B1))
#define CP_ASYNC4(DST, SRC) \
    asm volatile("cp.async.ca.shared.global [%0], [%1], 4;" :: "r"(DST), "l"(SRC))
#define CP_COMMIT() asm volatile("cp.async.commit_group;" ::: "memory")
#define CP_WAIT0()  asm volatile("cp.async.wait_group 0;" ::: "memory")

// ---------------------------------------------------------------------------
__global__ __launch_bounds__(128)
void nf_kernel(const float* __restrict__ features,
               const float* __restrict__ W_f,
               const float* __restrict__ b_f) {
    __shared__ float fs[H_];
    const int row = blockIdx.x;
    const int f   = threadIdx.x;
    fs[f] = features[(size_t)row * H_ + f];
    __syncthreads();
    float acc = b_f[f];
#pragma unroll 8
    for (int h = 0; h < H_; ++h) acc = fmaf(fs[h], W_f[h * F_ + f], acc);
    g_nf[(size_t)row * F_ + f] = acc;
}

// ---------------------------------------------------------------------------
__device__ __forceinline__ void compact_mask(const int* __restrict__ mb, int* jl,
                                             int* cnt_slot, int* iscr,
                                             int gtid, int wg, int lane, int barid) {
    const int m = (gtid < N_) ? mb[gtid] : 0;
    int v = m;
#pragma unroll
    for (int o = 1; o < 32; o <<= 1) {
        int nv = __shfl_up_sync(0xffffffffu, v, o);
        if (lane >= o) v += nv;
    }
    if (lane == 31) iscr[wg] = v;
    gbar(barid, 256);
    int base = 0;
    for (int w = 0; w < wg; ++w) base += iscr[w];
    if (gtid < N_ && m) jl[base + v - m] = gtid;
    if (gtid == 0) {
        int c = 0;
#pragma unroll
        for (int w = 0; w < 8; ++w) c += iscr[w];
        cnt_slot[0] = c;
    }
    gbar(barid, 256);
}

__device__ __forceinline__ void issue_gather(const float* __restrict__ rbfb,
                                             const int* __restrict__ jl, int cnt,
                                             uint32_t fst_sa, int gtid) {
    for (int idx = gtid; idx < TM * G_; idx += 256) {
        const int r = (idx * 5243) >> 18;   // idx / 50
        const int c = idx - r * G_;
        if (r < cnt) {
            const float* src = rbfb + (size_t)jl[r] * G_ + c;
            CP_ASYNC4(fst_sa + idx * 4, src);
        }
    }
    CP_COMMIT();
}

__device__ __forceinline__ void convert_fst(const float* __restrict__ fst,
                                            __half* rbh, float* wt, int* jr,
                                            const int* __restrict__ jl, int cnt, int gtid) {
    for (int idx = gtid; idx < TM * G_; idx += 256) {
        const int r = (idx * 5243) >> 18;
        const int c = idx - r * G_;
        const float v = (r < cnt) ? fst[idx] : 0.0f;
        rbh[r * LDA1 + c] = __float2half_rn(v);
    }
    if (gtid < TM) {
        const bool ok = gtid < cnt;
        wt[gtid] = ok ? 1.0f : 0.0f;
        jr[gtid] = ok ? jl[gtid] : 0;
    }
}

// ---------------------------------------------------------------------------
__global__ __launch_bounds__(768, 1)
void interaction_kernel(const float* __restrict__ rbf,
                        const int*   __restrict__ nmask,
                        const float* __restrict__ W1,
                        const float* __restrict__ b1,
                        const float* __restrict__ W2,
                        const float* __restrict__ b2,
                        const float* __restrict__ Wo1,
                        const float* __restrict__ bo1,
                        const float* __restrict__ Wo2,
                        const float* __restrict__ bo2,
                        const float* __restrict__ features,
                        float*       __restrict__ out) {
    extern __shared__ char smem[];
    const uint32_t sb = (uint32_t)__cvta_generic_to_shared(smem);

    const int tid  = threadIdx.x;
    const int g    = tid >> 8;
    const int gtid = tid & 255;
    const int wg   = gtid >> 5;
    const int lane = tid & 31;

    __half* W1h = (__half*)(smem + W1_OFF);
    __half* W2h = (__half*)(smem + W2_OFF);
    char*   gsm = smem + GRP0_OFF + g * GRP_BYTES;
    __half* rbh   = (__half*)(gsm + RBH_OFF);
    float*  fst   = (float*)(gsm + FST_OFF);
    float*  wt_s  = (float*)(gsm + WT_OFF);
    int*    jr_s  = (int*)(gsm + JR_OFF);
    int*    jl0   = (int*)(gsm + JL_OFF);
    float*  red   = (float*)(gsm + RED_OFF);
    float*  b1_s  = (float*)(gsm + B1_OFF);
    float*  b2_s  = (float*)(gsm + B2_OFF);
    int*    cnt_s = (int*)(gsm + CNT_OFF);          // [2]
    int*    iscr  = cnt_s + 2;                      // [8]
    float*  sc    = (float*)(gsm + SC_OFF);         // [256]

    const uint32_t fst_sa = sb + (uint32_t)(GRP0_OFF + g * GRP_BYTES + FST_OFF);

    // ---- stage weights fp16 once (biases go to accumulator init) ----
    for (int idx = tid; idx < 64 * F_; idx += 768) {
        const int k = idx >> 7, n = idx & 127;
        W1h[k * LDB + n] = __float2half_rn((k < G_) ? W1[k * F_ + n] : 0.0f);
    }
    for (int idx = tid; idx < F_ * F_; idx += 768) {
        const int k = idx >> 7, n = idx & 127;
        W2h[k * LDB + n] = __float2half_rn(W2[idx]);
    }
    if (gtid < 128) { b1_s[gtid] = b1[gtid]; b2_s[gtid] = b2[gtid]; }
    for (int idx = gtid; idx < 8 * 128; idx += 256) red[idx] = 0.0f;
    for (int idx = gtid; idx < TM * 14; idx += 256) {      // rbh pad cols 50..63
        const int r = idx / 14, c = G_ + idx - (idx / 14) * 14;
        rbh[r * LDA1 + c] = __float2half_rn(0.0f);
    }
    __syncthreads();

    const int first = blockIdx.x * NG + g;
    const int niter = (ATOMS - 1 - first) / GSTRIDE + 1;

    const int qrow = lane >> 2;
    const int qcol = (lane & 3) * 2;
    const int arow = lane & 15;
    const int asel = (lane >> 4) * 8;
    const uint32_t aA1 = sb + (uint32_t)(GRP0_OFF + g * GRP_BYTES + RBH_OFF)
                       + ((wg * 16 + arow) * LDA1 + asel) * 2;
    const uint32_t aW1 = sb + W1_OFF + (arow * LDB + asel) * 2;
    const uint32_t aW2 = sb + W2_OFF + (arow * LDB + asel) * 2;

    // ---- prologue: compact + gather + convert atom 0 ----
    int p = 0;
    {
        compact_mask(nmask + (size_t)first * N_, jl0, cnt_s, iscr, gtid, wg, lane, g + 1);
        issue_gather(rbf + (size_t)first * N_ * G_, jl0, cnt_s[0], fst_sa, gtid);
        CP_WAIT0();
        gbar(g + 1, 256);
        convert_fst(fst, rbh, wt_s, jr_s, jl0, cnt_s[0], gtid);
        gbar(g + 1, 256);
    }

    for (int it = 0; it < niter; ++it) {
        const int atom = first + it * GSTRIDE;
        const int cnt  = cnt_s[p];
        const bool hasnext = (it + 1) < niter;
        const int  b  = atom / N_;
        const float* nf_b = g_nf + (size_t)b * N_ * F_;
        int* jlc = jl0 + p * 192;
        int* jln = jl0 + (p ^ 1) * 192;

        // ---- issue next atom's compaction + async gather ----
        if (hasnext) {
            const int nxt = atom + GSTRIDE;
            compact_mask(nmask + (size_t)nxt * N_, jln, cnt_s + (p ^ 1), iscr,
                         gtid, wg, lane, g + 1);
            issue_gather(rbf + (size_t)nxt * N_ * G_, jln, cnt_s[p ^ 1], fst_sa, gtid);
        }

        // ---- compute tiles of current atom ----
        const int tcount = (cnt + TM - 1) >> 7;     // 1 except cnt>128 (rare)
        for (int t = 0; t < tcount; ++t) {
            if (t) {   // rare slow path: sync re-gather rows 128..cnt-1
                gbar(g + 1, 256);
                const float* rbfb = rbf + (size_t)atom * N_ * G_;
                for (int idx = gtid; idx < TM * G_; idx += 256) {
                    const int r = (idx * 5243) >> 18;
                    const int c = idx - r * G_;
                    const int rowpos = t * TM + r;
                    float v = 0.0f;
                    if (rowpos < cnt) v = rbfb[(size_t)jlc[rowpos] * G_ + c];
                    rbh[r * LDA1 + c] = __float2half_rn(v);
                }
                if (gtid < TM) {
                    const int rowpos = t * TM + gtid;
                    const bool ok = rowpos < cnt;
                    wt_s[gtid] = ok ? 1.0f : 0.0f;
                    jr_s[gtid] = ok ? jlc[rowpos] : 0;
                }
                gbar(g + 1, 256);
            }

            if (t * TM + wg * 16 < cnt) {
                // GEMM1: [16,64]@[64,128] in two n-halves -> softplus -> A2 regs
                uint32_t A2[8][4];
#pragma unroll
                for (int h2 = 0; h2 < 2; ++h2) {
                    float c1[8][4];
#pragma unroll
                    for (int nb = 0; nb < 8; ++nb) {
                        const float2 bv = *(const float2*)(b1_s + h2 * 64 + nb * 8 + qcol);
                        c1[nb][0] = bv.x; c1[nb][1] = bv.y;
                        c1[nb][2] = bv.x; c1[nb][3] = bv.y;
                    }
#pragma unroll
                    for (int ks = 0; ks < 4; ++ks) {
                        uint32_t a[4];
                        LDSM4(a, aA1 + ks * 32);
#pragma unroll
                        for (int pp = 0; pp < 4; ++pp) {
                            uint32_t bb[4];
                            LDSM4T(bb, aW1 + (ks * 16 * LDB + h2 * 64 + pp * 16) * 2);
                            MMA16816(c1[pp * 2],     a, bb[0], bb[1]);
                            MMA16816(c1[pp * 2 + 1], a, bb[2], bb[3]);
                        }
                    }
#pragma unroll
                    for (int gk = 0; gk < 4; ++gk) {
                        A2[h2 * 4 + gk][0] = packh2(softplus_fast(c1[2 * gk][0]),
                                                    softplus_fast(c1[2 * gk][1]));
                        A2[h2 * 4 + gk][1] = packh2(softplus_fast(c1[2 * gk][2]),
                                                    softplus_fast(c1[2 * gk][3]));
                        A2[h2 * 4 + gk][2] = packh2(softplus_fast(c1[2 * gk + 1][0]),
                                                    softplus_fast(c1[2 * gk + 1][1]));
                        A2[h2 * 4 + gk][3] = packh2(softplus_fast(c1[2 * gk + 1][2]),
                                                    softplus_fast(c1[2 * gk + 1][3]));
                    }
                }

                // GEMM2: [16,128]@[128,128] in 4 n-chunks + fused aggregation
                const int r0 = wg * 16 + qrow;
                const float w0 = wt_s[r0];
                const float w1 = wt_s[r0 + 8];
                const float* nr0 = nf_b + (size_t)jr_s[r0] * F_;
                const float* nr1 = nf_b + (size_t)jr_s[r0 + 8] * F_;
                float* redw = red + wg * 128;
#pragma unroll
                for (int ch = 0; ch < 4; ++ch) {
                    const int cc0 = ch * 32;
                    float c2[4][4];
#pragma unroll
                    for (int ni = 0; ni < 4; ++ni) {
                        const float2 bv = *(const float2*)(b2_s + cc0 + ni * 8 + qcol);
                        c2[ni][0] = bv.x; c2[ni][1] = bv.y;
                        c2[ni][2] = bv.x; c2[ni][3] = bv.y;
                    }
#pragma unroll
                    for (int ks = 0; ks < 8; ++ks) {
                        uint32_t bb0[4], bb1[4];
                        LDSM4T(bb0, aW2 + (ks * 16 * LDB + cc0) * 2);
                        LDSM4T(bb1, aW2 + (ks * 16 * LDB + cc0 + 16) * 2);
                        MMA16816(c2[0], A2[ks], bb0[0], bb0[1]);
                        MMA16816(c2[1], A2[ks], bb0[2], bb0[3]);
                        MMA16816(c2[2], A2[ks], bb1[0], bb1[1]);
                        MMA16816(c2[3], A2[ks], bb1[2], bb1[3]);
                    }
#pragma unroll
                    for (int ni = 0; ni < 4; ++ni) {
                        const int cc = cc0 + ni * 8 + qcol;
                        const float2 v0 = *(const float2*)(nr0 + cc);
                        const float2 v1 = *(const float2*)(nr1 + cc);
                        float s0 = c2[ni][0] * w0 * v0.x + c2[ni][2] * w1 * v1.x;
                        float s1 = c2[ni][1] * w0 * v0.y + c2[ni][3] * w1 * v1.y;
                        s0 += __shfl_xor_sync(0xffffffffu, s0, 4);
                        s0 += __shfl_xor_sync(0xffffffffu, s0, 8);
                        s0 += __shfl_xor_sync(0xffffffffu, s0, 16);
                        s1 += __shfl_xor_sync(0xffffffffu, s1, 4);
                        s1 += __shfl_xor_sync(0xffffffffu, s1, 8);
                        s1 += __shfl_xor_sync(0xffffffffu, s1, 16);
                        if (lane < 4) {
                            redw[cc]     += s0;
                            redw[cc + 1] += s1;
                        }
                    }
                }
            }
        }
        gbar(g + 1, 256);

        // ---- epilogue (128 threads): reduce+rezero red, MLP, residual ----
        if (gtid < 128) {
            float a = 0.0f;
#pragma unroll
            for (int w = 0; w < 8; ++w) {
                a += red[w * 128 + gtid];
                red[w * 128 + gtid] = 0.0f;
            }
            sc[gtid] = a;
            gbar(g + 4, 128);

            float t1 = bo1[gtid];
#pragma unroll 8
            for (int f = 0; f < F_; ++f) t1 = fmaf(sc[f], Wo1[f * H_ + gtid], t1);
            t1 = softplus_fast(t1);
            sc[128 + gtid] = t1;
            gbar(g + 4, 128);

            float o = bo2[gtid];
#pragma unroll 8
            for (int f = 0; f < F_; ++f) o = fmaf(sc[128 + f], Wo2[f * H_ + gtid], o);
            out[(size_t)atom * H_ + gtid] = o + features[(size_t)atom * H_ + gtid];
        }

        // ---- land next atom's gather, convert to fp16 ----
        CP_WAIT0();
        gbar(g + 1, 256);
        if (hasnext) {
            convert_fst(fst, rbh, wt_s, jr_s, jln, cnt_s[p ^ 1], gtid);
            gbar(g + 1, 256);
        }
        p ^= 1;
    }
}

// ---------------------------------------------------------------------------
extern "C" void kernel_launch(void* const* d_in, const int* in_sizes, int n_in,
                              void* d_out, int out_size) {
    const float* features = (const float*)d_in[0];
    const float* rbf      = (const float*)d_in[1];
    const int*   nmask    = (const int*)  d_in[2];
    const float* W_rbf1   = (const float*)d_in[3];
    const float* b_rbf1   = (const float*)d_in[4];
    const float* W_rbf2   = (const float*)d_in[5];
    const float* b_rbf2   = (const float*)d_in[6];
    const float* W_f      = (const float*)d_in[7];
    const float* b_f      = (const float*)d_in[8];
    const float* W_o1     = (const float*)d_in[9];
    const float* b_o1     = (const float*)d_in[10];
    const float* W_o2     = (const float*)d_in[11];
    const float* b_o2     = (const float*)d_in[12];
    float* out = (float*)d_out;

    static int configured = -1;
    if (configured < 0) {
        cudaFuncSetAttribute(interaction_kernel,
                             cudaFuncAttributeMaxDynamicSharedMemorySize, SMEM_BYTES);
        configured = 1;
    }

    nf_kernel<<<B_ * N_, 128>>>(features, W_f, b_f);
    interaction_kernel<<<GRID, 768, SMEM_BYTES>>>(
        rbf, nmask, W_rbf1, b_rbf1, W_rbf2, b_rbf2,
        W_o1, b_o1, W_o2, b_o2, features, out);
}

// round 16
// speedup vs baseline: 10.0374x; 1.2205x over previous
#include <cuda_runtime.h>
#include <cuda_fp16.h>
#include <cstdint>

#define B_  16
#define N_  192
#define H_  128
#define F_  128
#define G_  50
#define NG  3        // atom groups per CTA (256 threads each)
#define TM  128      // tile rows (8 warps x 16)
#define LDA1 72      // rbh row stride (halfs)
#define LDB  136     // weight row stride (halfs)
#define ATOMS (B_ * N_)
#define GRID 152
#define GSTRIDE (GRID * NG)   // 456

// group byte offsets
#define RBH_OFF 0                        // 128*72*2 = 18432
#define FST_OFF 18432                    // 128*50*4 = 25600 float staging
#define WT_OFF  44032                    // 128 floats
#define JR_OFF  44544                    // 128 ints
#define JL_OFF  45056                    // 2 x 192 ints
#define RED_OFF 46592                    // 8*128 floats
#define B1_OFF  50688                    // 128 floats
#define B2_OFF  51200                    // 128 floats
#define CNT_OFF 51712                    // cnt[2] + iscr[8]
#define GRP_BYTES 51776

#define W1_OFF 0                         // 64*136*2  = 17408
#define W2_OFF 17408                     // 128*136*2 = 34816
#define GRP0_OFF 52224
#define SMEM_BYTES (GRP0_OFF + NG * GRP_BYTES)   // 207552

__device__ float g_nf[B_ * N_ * F_];
__device__ float g_agg[ATOMS * F_];

__device__ __forceinline__ float softplus_fast(float x) {
    float ax = fabsf(x);
    return fmaxf(x, 0.0f) + __logf(1.0f + __expf(-ax));
}
__device__ __forceinline__ void gbar(int id, int cnt) {
    asm volatile("bar.sync %0, %1;" :: "r"(id), "r"(cnt) : "memory");
}
__device__ __forceinline__ uint32_t packh2(float a, float b) {
    __half2 h = __floats2half2_rn(a, b);
    return *reinterpret_cast<uint32_t*>(&h);
}

#define LDSM4(R, ADDR) \
    asm volatile("ldmatrix.sync.aligned.m8n8.x4.shared.b16 {%0,%1,%2,%3}, [%4];" \
        : "=r"((R)[0]), "=r"((R)[1]), "=r"((R)[2]), "=r"((R)[3]) : "r"(ADDR))
#define LDSM4T(R, ADDR) \
    asm volatile("ldmatrix.sync.aligned.m8n8.x4.trans.shared.b16 {%0,%1,%2,%3}, [%4];" \
        : "=r"((R)[0]), "=r"((R)[1]), "=r"((R)[2]), "=r"((R)[3]) : "r"(ADDR))
#define MMA16816(C, A, B0, B1) \
    asm volatile("mma.sync.aligned.m16n8k16.row.col.f32.f16.f16.f32 " \
        "{%0,%1,%2,%3}, {%4,%5,%6,%7}, {%8,%9}, {%0,%1,%2,%3};" \
        : "+f"((C)[0]), "+f"((C)[1]), "+f"((C)[2]), "+f"((C)[3]) \
        : "r"((A)[0]), "r"((A)[1]), "r"((A)[2]), "r"((A)[3]), "r"(B0), "r"(B1))
#define CP_ASYNC8(DST, SRC) \
    asm volatile("cp.async.ca.shared.global [%0], [%1], 8;" :: "r"(DST), "l"(SRC))
#define CP_COMMIT() asm volatile("cp.async.commit_group;" ::: "memory")
#define CP_WAIT0()  asm volatile("cp.async.wait_group 0;" ::: "memory")

// ---------------------------------------------------------------------------
__global__ __launch_bounds__(128)
void nf_kernel(const float* __restrict__ features,
               const float* __restrict__ W_f,
               const float* __restrict__ b_f) {
    __shared__ float fs[H_];
    const int row = blockIdx.x;
    const int f   = threadIdx.x;
    fs[f] = features[(size_t)row * H_ + f];
    __syncthreads();
    float acc = b_f[f];
#pragma unroll 8
    for (int h = 0; h < H_; ++h) acc = fmaf(fs[h], W_f[h * F_ + f], acc);
    g_nf[(size_t)row * F_ + f] = acc;
}

// ---------------------------------------------------------------------------
__device__ __forceinline__ void compact_mask(const int* __restrict__ mb, int* jl,
                                             int* cnt_slot, int* iscr,
                                             int gtid, int wg, int lane, int barid) {
    const int m = (gtid < N_) ? mb[gtid] : 0;
    int v = m;
#pragma unroll
    for (int o = 1; o < 32; o <<= 1) {
        int nv = __shfl_up_sync(0xffffffffu, v, o);
        if (lane >= o) v += nv;
    }
    if (lane == 31) iscr[wg] = v;
    gbar(barid, 256);
    int base = 0;
    for (int w = 0; w < wg; ++w) base += iscr[w];
    if (gtid < N_ && m) jl[base + v - m] = gtid;
    if (gtid == 0) {
        int c = 0;
#pragma unroll
        for (int w = 0; w < 8; ++w) c += iscr[w];
        cnt_slot[0] = c;
    }
    gbar(barid, 256);
}

// 8-byte async gather of compacted rows (rows are 200B, 8B-aligned)
__device__ __forceinline__ void issue_gather(const float* __restrict__ rbfb,
                                             const int* __restrict__ jl, int cnt,
                                             uint32_t fst_sa, int gtid) {
    for (int idx = gtid; idx < TM * 25; idx += 256) {
        const int r  = (idx * 5243) >> 17;    // idx / 25
        const int c2 = (idx - r * 25) * 2;
        if (r < cnt) {
            const float* src = rbfb + (size_t)jl[r] * G_ + c2;
            CP_ASYNC8(fst_sa + idx * 8, src);
        }
    }
    CP_COMMIT();
}

__device__ __forceinline__ void convert_fst(const float* __restrict__ fst,
                                            __half* rbh, float* wt, int* jr,
                                            const int* __restrict__ jl, int cnt, int gtid) {
    for (int idx = gtid; idx < TM * 25; idx += 256) {
        const int r  = (idx * 5243) >> 17;
        const int c2 = (idx - r * 25) * 2;
        float2 v = make_float2(0.0f, 0.0f);
        if (r < cnt) v = *(const float2*)(fst + idx * 2);
        *(__half2*)(rbh + r * LDA1 + c2) = __floats2half2_rn(v.x, v.y);
    }
    if (gtid < TM) {
        const bool ok = gtid < cnt;
        wt[gtid] = ok ? 1.0f : 0.0f;
        jr[gtid] = ok ? jl[gtid] : 0;
    }
}

// ---------------------------------------------------------------------------
__global__ __launch_bounds__(768, 1)
void interaction_kernel(const float* __restrict__ rbf,
                        const int*   __restrict__ nmask,
                        const float* __restrict__ W1,
                        const float* __restrict__ b1,
                        const float* __restrict__ W2,
                        const float* __restrict__ b2) {
    extern __shared__ char smem[];
    const uint32_t sb = (uint32_t)__cvta_generic_to_shared(smem);

    const int tid  = threadIdx.x;
    const int g    = tid >> 8;
    const int gtid = tid & 255;
    const int wg   = gtid >> 5;
    const int lane = tid & 31;

    __half* W1h = (__half*)(smem + W1_OFF);
    __half* W2h = (__half*)(smem + W2_OFF);
    char*   gsm = smem + GRP0_OFF + g * GRP_BYTES;
    __half* rbh   = (__half*)(gsm + RBH_OFF);
    float*  fst   = (float*)(gsm + FST_OFF);
    float*  wt_s  = (float*)(gsm + WT_OFF);
    int*    jr_s  = (int*)(gsm + JR_OFF);
    int*    jl0   = (int*)(gsm + JL_OFF);
    float*  red   = (float*)(gsm + RED_OFF);
    float*  b1_s  = (float*)(gsm + B1_OFF);
    float*  b2_s  = (float*)(gsm + B2_OFF);
    int*    cnt_s = (int*)(gsm + CNT_OFF);          // [2]
    int*    iscr  = cnt_s + 2;                      // [8]

    const uint32_t fst_sa = sb + (uint32_t)(GRP0_OFF + g * GRP_BYTES + FST_OFF);

    // ---- stage weights fp16 once ----
    for (int idx = tid; idx < 64 * F_; idx += 768) {
        const int k = idx >> 7, n = idx & 127;
        W1h[k * LDB + n] = __float2half_rn((k < G_) ? W1[k * F_ + n] : 0.0f);
    }
    for (int idx = tid; idx < F_ * F_; idx += 768) {
        const int k = idx >> 7, n = idx & 127;
        W2h[k * LDB + n] = __float2half_rn(W2[idx]);
    }
    if (gtid < 128) { b1_s[gtid] = b1[gtid]; b2_s[gtid] = b2[gtid]; }
    for (int idx = gtid; idx < 8 * 128; idx += 256) red[idx] = 0.0f;
    for (int idx = gtid; idx < TM * 14; idx += 256) {      // rbh pad cols 50..63
        const int r = idx / 14, c = G_ + idx - (idx / 14) * 14;
        rbh[r * LDA1 + c] = __float2half_rn(0.0f);
    }
    __syncthreads();

    const int first = blockIdx.x * NG + g;
    const int niter = (ATOMS - 1 - first) / GSTRIDE + 1;

    const int qrow = lane >> 2;
    const int qcol = (lane & 3) * 2;
    const int arow = lane & 15;
    const int asel = (lane >> 4) * 8;
    const uint32_t aA1 = sb + (uint32_t)(GRP0_OFF + g * GRP_BYTES + RBH_OFF)
                       + ((wg * 16 + arow) * LDA1 + asel) * 2;
    const uint32_t aW1 = sb + W1_OFF + (arow * LDB + asel) * 2;
    const uint32_t aW2 = sb + W2_OFF + (arow * LDB + asel) * 2;

    // ---- prologue: compact + gather + convert atom 0 ----
    int p = 0;
    {
        compact_mask(nmask + (size_t)first * N_, jl0, cnt_s, iscr, gtid, wg, lane, g + 1);
        issue_gather(rbf + (size_t)first * N_ * G_, jl0, cnt_s[0], fst_sa, gtid);
        CP_WAIT0();
        gbar(g + 1, 256);
        convert_fst(fst, rbh, wt_s, jr_s, jl0, cnt_s[0], gtid);
        gbar(g + 1, 256);
    }

    for (int it = 0; it < niter; ++it) {
        const int atom = first + it * GSTRIDE;
        const int cnt  = cnt_s[p];
        const bool hasnext = (it + 1) < niter;
        const int  b  = atom / N_;
        const float* nf_b = g_nf + (size_t)b * N_ * F_;
        int* jlc = jl0 + p * 192;
        int* jln = jl0 + (p ^ 1) * 192;

        // ---- issue next atom's compaction + async gather ----
        if (hasnext) {
            const int nxt = atom + GSTRIDE;
            compact_mask(nmask + (size_t)nxt * N_, jln, cnt_s + (p ^ 1), iscr,
                         gtid, wg, lane, g + 1);
            issue_gather(rbf + (size_t)nxt * N_ * G_, jln, cnt_s[p ^ 1], fst_sa, gtid);
        }

        // ---- compute tiles of current atom ----
        const int tcount = (cnt + TM - 1) >> 7;     // 1 except cnt>128 (rare)
        for (int t = 0; t < tcount; ++t) {
            if (t) {   // rare slow path: sync re-gather rows 128..cnt-1
                gbar(g + 1, 256);
                const float* rbfb = rbf + (size_t)atom * N_ * G_;
                for (int idx = gtid; idx < TM * G_; idx += 256) {
                    const int r = (idx * 5243) >> 18;
                    const int c = idx - r * G_;
                    const int rowpos = t * TM + r;
                    float v = 0.0f;
                    if (rowpos < cnt) v = rbfb[(size_t)jlc[rowpos] * G_ + c];
                    rbh[r * LDA1 + c] = __float2half_rn(v);
                }
                if (gtid < TM) {
                    const int rowpos = t * TM + gtid;
                    const bool ok = rowpos < cnt;
                    wt_s[gtid] = ok ? 1.0f : 0.0f;
                    jr_s[gtid] = ok ? jlc[rowpos] : 0;
                }
                gbar(g + 1, 256);
            }

            if (t * TM + wg * 16 < cnt) {
                // GEMM1: [16,64]@[64,128] in two n-halves -> softplus -> A2 regs
                uint32_t A2[8][4];
#pragma unroll
                for (int h2 = 0; h2 < 2; ++h2) {
                    float c1[8][4];
#pragma unroll
                    for (int nb = 0; nb < 8; ++nb) {
                        const float2 bv = *(const float2*)(b1_s + h2 * 64 + nb * 8 + qcol);
                        c1[nb][0] = bv.x; c1[nb][1] = bv.y;
                        c1[nb][2] = bv.x; c1[nb][3] = bv.y;
                    }
#pragma unroll
                    for (int ks = 0; ks < 4; ++ks) {
                        uint32_t a[4];
                        LDSM4(a, aA1 + ks * 32);
#pragma unroll
                        for (int pp = 0; pp < 4; ++pp) {
                            uint32_t bb[4];
                            LDSM4T(bb, aW1 + (ks * 16 * LDB + h2 * 64 + pp * 16) * 2);
                            MMA16816(c1[pp * 2],     a, bb[0], bb[1]);
                            MMA16816(c1[pp * 2 + 1], a, bb[2], bb[3]);
                        }
                    }
#pragma unroll
                    for (int gk = 0; gk < 4; ++gk) {
                        A2[h2 * 4 + gk][0] = packh2(softplus_fast(c1[2 * gk][0]),
                                                    softplus_fast(c1[2 * gk][1]));
                        A2[h2 * 4 + gk][1] = packh2(softplus_fast(c1[2 * gk][2]),
                                                    softplus_fast(c1[2 * gk][3]));
                        A2[h2 * 4 + gk][2] = packh2(softplus_fast(c1[2 * gk + 1][0]),
                                                    softplus_fast(c1[2 * gk + 1][1]));
                        A2[h2 * 4 + gk][3] = packh2(softplus_fast(c1[2 * gk + 1][2]),
                                                    softplus_fast(c1[2 * gk + 1][3]));
                    }
                }

                // GEMM2: [16,128]@[128,128] in 4 n-chunks + fused aggregation
                const int r0 = wg * 16 + qrow;
                const float w0 = wt_s[r0];
                const float w1 = wt_s[r0 + 8];
                const float* nr0 = nf_b + (size_t)jr_s[r0] * F_;
                const float* nr1 = nf_b + (size_t)jr_s[r0 + 8] * F_;
                float* redw = red + wg * 128;
#pragma unroll
                for (int ch = 0; ch < 4; ++ch) {
                    const int cc0 = ch * 32;
                    float c2[4][4];
#pragma unroll
                    for (int ni = 0; ni < 4; ++ni) {
                        const float2 bv = *(const float2*)(b2_s + cc0 + ni * 8 + qcol);
                        c2[ni][0] = bv.x; c2[ni][1] = bv.y;
                        c2[ni][2] = bv.x; c2[ni][3] = bv.y;
                    }
#pragma unroll
                    for (int ks = 0; ks < 8; ++ks) {
                        uint32_t bb0[4], bb1[4];
                        LDSM4T(bb0, aW2 + (ks * 16 * LDB + cc0) * 2);
                        LDSM4T(bb1, aW2 + (ks * 16 * LDB + cc0 + 16) * 2);
                        MMA16816(c2[0], A2[ks], bb0[0], bb0[1]);
                        MMA16816(c2[1], A2[ks], bb0[2], bb0[3]);
                        MMA16816(c2[2], A2[ks], bb1[0], bb1[1]);
                        MMA16816(c2[3], A2[ks], bb1[2], bb1[3]);
                    }
#pragma unroll
                    for (int ni = 0; ni < 4; ++ni) {
                        const int cc = cc0 + ni * 8 + qcol;
                        const float2 v0 = *(const float2*)(nr0 + cc);
                        const float2 v1 = *(const float2*)(nr1 + cc);
                        float s0 = c2[ni][0] * w0 * v0.x + c2[ni][2] * w1 * v1.x;
                        float s1 = c2[ni][1] * w0 * v0.y + c2[ni][3] * w1 * v1.y;
                        s0 += __shfl_xor_sync(0xffffffffu, s0, 4);
                        s0 += __shfl_xor_sync(0xffffffffu, s0, 8);
                        s0 += __shfl_xor_sync(0xffffffffu, s0, 16);
                        s1 += __shfl_xor_sync(0xffffffffu, s1, 4);
                        s1 += __shfl_xor_sync(0xffffffffu, s1, 8);
                        s1 += __shfl_xor_sync(0xffffffffu, s1, 16);
                        if (lane < 4) {
                            redw[cc]     += s0;
                            redw[cc + 1] += s1;
                        }
                    }
                }
            }
        }
        gbar(g + 1, 256);

        // ---- reduce + store agg to global; MLP is a separate kernel ----
        if (gtid < 128) {
            float a = 0.0f;
#pragma unroll
            for (int w = 0; w < 8; ++w) {
                a += red[w * 128 + gtid];
                red[w * 128 + gtid] = 0.0f;
            }
            g_agg[(size_t)atom * F_ + gtid] = a;
        }

        // ---- land next atom's gather, convert to fp16 ----
        CP_WAIT0();
        gbar(g + 1, 256);
        if (hasnext) {
            convert_fst(fst, rbh, wt_s, jr_s, jln, cnt_s[p ^ 1], gtid);
            gbar(g + 1, 256);
        }
        p ^= 1;
    }
}

// ---------------------------------------------------------------------------
// out = softplus(agg @ Wo1 + bo1) @ Wo2 + bo2 + features, tiled 16 rows/CTA
#define OUT_R 16
__global__ __launch_bounds__(256)
void out_kernel(const float* __restrict__ Wo1,
                const float* __restrict__ bo1,
                const float* __restrict__ Wo2,
                const float* __restrict__ bo2,
                const float* __restrict__ features,
                float*       __restrict__ out) {
    __shared__ float aggs[OUT_R][128];
    __shared__ float t1s[OUT_R][128];
    const int r0   = blockIdx.x * OUT_R;
    const int tid  = threadIdx.x;
    const int col  = tid & 127;
    const int half = tid >> 7;

    for (int i = tid; i < OUT_R * 128; i += 256)
        aggs[i >> 7][i & 127] = g_agg[(size_t)r0 * 128 + i];
    __syncthreads();

    float acc[OUT_R / 2];
#pragma unroll
    for (int r = 0; r < OUT_R / 2; ++r) acc[r] = bo1[col];
    for (int f = 0; f < 128; ++f) {
        const float w = Wo1[f * 128 + col];
#pragma unroll
        for (int r = 0; r < OUT_R / 2; ++r)
            acc[r] = fmaf(aggs[half + 2 * r][f], w, acc[r]);
    }
#pragma unroll
    for (int r = 0; r < OUT_R / 2; ++r)
        t1s[half + 2 * r][col] = softplus_fast(acc[r]);
    __syncthreads();

#pragma unroll
    for (int r = 0; r < OUT_R / 2; ++r) acc[r] = bo2[col];
    for (int f = 0; f < 128; ++f) {
        const float w = Wo2[f * 128 + col];
#pragma unroll
        for (int r = 0; r < OUT_R / 2; ++r)
            acc[r] = fmaf(t1s[half + 2 * r][f], w, acc[r]);
    }
#pragma unroll
    for (int r = 0; r < OUT_R / 2; ++r) {
        const size_t row = r0 + half + 2 * r;
        out[row * 128 + col] = acc[r] + features[row * 128 + col];
    }
}

// ---------------------------------------------------------------------------
extern "C" void kernel_launch(void* const* d_in, const int* in_sizes, int n_in,
                              void* d_out, int out_size) {
    const float* features = (const float*)d_in[0];
    const float* rbf      = (const float*)d_in[1];
    const int*   nmask    = (const int*)  d_in[2];
    const float* W_rbf1   = (const float*)d_in[3];
    const float* b_rbf1   = (const float*)d_in[4];
    const float* W_rbf2   = (const float*)d_in[5];
    const float* b_rbf2   = (const float*)d_in[6];
    const float* W_f      = (const float*)d_in[7];
    const float* b_f      = (const float*)d_in[8];
    const float* W_o1     = (const float*)d_in[9];
    const float* b_o1     = (const float*)d_in[10];
    const float* W_o2     = (const float*)d_in[11];
    const float* b_o2     = (const float*)d_in[12];
    float* out = (float*)d_out;

    static int configured = -1;
    if (configured < 0) {
        cudaFuncSetAttribute(interaction_kernel,
                             cudaFuncAttributeMaxDynamicSharedMemorySize, SMEM_BYTES);
        configured = 1;
    }

    nf_kernel<<<B_ * N_, 128>>>(features, W_f, b_f);
    interaction_kernel<<<GRID, 768, SMEM_BYTES>>>(
        rbf, nmask, W_rbf1, b_rbf1, W_rbf2, b_rbf2);
    out_kernel<<<ATOMS / OUT_R, 256>>>(W_o1, b_o1, W_o2, b_o2, features, out);
}